// round 13
// baseline (speedup 1.0000x reference)
#include <cuda_runtime.h>
#include <cuda_bf16.h>
#include <stdint.h>
#include <math.h>

#define N_NODES 50000
#define N_EDGES 800000
#define HID     128
#define OUT_DIM 40
#define N_LAYERS 4
#define N_GRAPHS 128
#define SCAN_B  49           // ceil(50000/1024)
#define EDGE_BLOCKS 3125     // ceil(800000/256)
#define WPREP_ELEMS (8 * HID * HID)
#define WPREP_BLOCKS ((WPREP_ELEMS + 255) / 256)
#define MTILES ((N_NODES + 127) / 128)     // 391
#define PERSIST_GRID 148                   // one wave, 1 CTA/SM
#define MMA_THREADS 512                    // 16 warps -> 4 per SMSP
#define FA_BLOCKS 148
#define FA_THREADS 1024

// ---------------- scratch (static device globals; zero-initialized at load) ----------------
__device__ float g_A[N_NODES * HID];                    // fp32 node features (layer output)
__device__ __nv_bfloat16 g_Bh[N_NODES * HID];           // agg output hi  (GEMM1 input)
__device__ __nv_bfloat16 g_Bl[N_NODES * HID];           // agg output lo
__device__ __nv_bfloat16 g_Ch[N_NODES * HID];           // GEMM1 output hi (GEMM2 input)
__device__ __nv_bfloat16 g_Cl[N_NODES * HID];           // GEMM1 output lo
__device__ __nv_bfloat16 g_Wth[WPREP_ELEMS];            // transposed weights hi: [mat][n][k]
__device__ __nv_bfloat16 g_Wtl[WPREP_ELEMS];            // transposed weights lo
__device__ int   g_rowoff[N_NODES + 1];                 // zeroed at load + k_pool tail
__device__ int   g_cursor[N_NODES];
__device__ int   g_srcs[N_EDGES];
__device__ volatile int g_bsum[SCAN_B];
__device__ volatile int g_bflag[SCAN_B];                // zeroed at load + k_pool tail
__device__ volatile int g_gbar;                         // fillagg grid barrier; reset in k_pool
__device__ int   g_is64;
__device__ float g_pooled[N_GRAPHS * HID];

// ---------------- helpers ----------------
__device__ __forceinline__ long long load_idx(const void* p, long long i, int is64) {
    if (is64) return ((const long long*)p)[i];
    return (long long)((const int*)p)[i];
}

__device__ __forceinline__ unsigned pack_bf(float a, float b) {
    __nv_bfloat162 t = __floats2bfloat162_rn(a, b);
    return *reinterpret_cast<unsigned*>(&t);
}

// ---------------- CSR count (by dst) + weight split/transpose (extra blocks) ----------------
__global__ void k_count(const void* __restrict__ edge,
                        const float* __restrict__ W1s, const float* __restrict__ W2s) {
    int b = blockIdx.x;
    if (b >= EDGE_BLOCKS) {
        // weight prep: Wt[mat][n][k] = W[mat][k][n] split into bf16 hi/lo
        int t = (b - EDGE_BLOCKS) * 256 + threadIdx.x;
        if (t < WPREP_ELEMS) {
            int mat = t >> 14, rem = t & 16383;
            int n = rem >> 7, k = rem & 127;
            int l = mat >> 1;
            float w = (mat & 1) ? W2s[l * 16384 + k * 128 + n]
                                : W1s[l * 16384 + k * 128 + n];
            __nv_bfloat16 h = __float2bfloat16(w);
            g_Wth[t] = h;
            g_Wtl[t] = __float2bfloat16(w - __bfloat162float(h));
        }
        return;
    }
    __shared__ int s_is64;
    int t = threadIdx.x;
    if (t == 0) s_is64 = 1;
    __syncthreads();
    if (t < 64) {
        // int32 data reinterpreted as int64 has a random node id in the high
        // word (invalid w.p. ~1), so 64 valid samples => genuine int64.
        long long v = ((const long long*)edge)[(long long)t * 12347 + 5];
        if (v < 0 || v >= N_NODES) atomicAnd(&s_is64, 0);
    }
    __syncthreads();
    int is64 = s_is64;
    if (b == 0 && t == 0) g_is64 = is64;
    int e = b * blockDim.x + t;
    if (e < N_EDGES) {
        int dst = (int)load_idx(edge, (long long)N_EDGES + e, is64);
        atomicAdd(&g_rowoff[dst], 1);
    }
}

// ---------------- single-kernel scan: block scan + decoupled lookback ----------------
__global__ void k_scanall() {
    __shared__ int part[1024];
    __shared__ int s_pref;
    int t = threadIdx.x, bid = blockIdx.x;
    int idx = bid * 1024 + t;
    int c = (idx < N_NODES) ? g_rowoff[idx] : 0;
    part[t] = c;
    __syncthreads();
    #pragma unroll
    for (int off = 1; off < 1024; off <<= 1) {
        int v = (t >= off) ? part[t - off] : 0;
        __syncthreads();
        part[t] += v;
        __syncthreads();
    }
    if (t == 1023) {
        g_bsum[bid] = part[1023];
        __threadfence();
        g_bflag[bid] = 1;
    }
    if (t < 32) {
        int s = 0;
        for (int p = t; p < bid; p += 32) {
            while (g_bflag[p] == 0) { }
            s += g_bsum[p];
        }
        #pragma unroll
        for (int o = 16; o; o >>= 1) s += __shfl_xor_sync(0xffffffffu, s, o);
        if (t == 0) s_pref = s;
    }
    __syncthreads();
    int pref = s_pref;
    if (idx < N_NODES) {
        int v = pref + part[t] - c;
        g_rowoff[idx] = v;
        g_cursor[idx] = v;
    }
    if (bid == SCAN_B - 1 && t == 1023) g_rowoff[N_NODES] = N_EDGES;
}

// ---------------- shared aggregation body ----------------
// h[w] = (1+eps)*x[w] + sum_{src->w} x[src], emitted as bf16 hi/lo
template <int U>
__device__ __forceinline__ void agg_node(const float4* __restrict__ x4, int w, int lane,
                                         float eps,
                                         __nv_bfloat16* __restrict__ oh,
                                         __nv_bfloat16* __restrict__ ol) {
    float4 a = x4[(long long)w * 32 + lane];
    float ax = a.x * eps, ay = a.y * eps, az = a.z * eps, aw = a.w * eps;
    int e = g_rowoff[w], end = g_rowoff[w + 1];
    for (; e + U - 1 < end; e += U) {
        int ss[U];
        float4 vv[U];
        #pragma unroll
        for (int j = 0; j < U; j++) ss[j] = g_srcs[e + j];
        #pragma unroll
        for (int j = 0; j < U; j++) vv[j] = x4[(long long)ss[j] * 32 + lane];
        #pragma unroll
        for (int j = 0; j < U; j++) {
            ax += vv[j].x; ay += vv[j].y; az += vv[j].z; aw += vv[j].w;
        }
    }
    for (; e < end; e++) {
        int s = g_srcs[e];
        float4 v = x4[(long long)s * 32 + lane];
        ax += v.x; ay += v.y; az += v.z; aw += v.w;
    }
    float hx = __bfloat162float(__float2bfloat16(ax));
    float hy = __bfloat162float(__float2bfloat16(ay));
    float hz = __bfloat162float(__float2bfloat16(az));
    float hw = __bfloat162float(__float2bfloat16(aw));
    uint2 H = make_uint2(pack_bf(hx, hy), pack_bf(hz, hw));
    uint2 L = make_uint2(pack_bf(ax - hx, ay - hy), pack_bf(az - hz, aw - hw));
    *(uint2*)(oh + (long long)w * 128 + lane * 4) = H;
    *(uint2*)(ol + (long long)w * 128 + lane * 4) = L;
}

// ---------------- fused CSR-fill + layer-0 aggregation (persistent, grid barrier) ----------------
__global__ void __launch_bounds__(FA_THREADS, 1)
k_fillagg(const void* __restrict__ edge, const float* __restrict__ xin,
          __nv_bfloat16* __restrict__ oh, __nv_bfloat16* __restrict__ ol,
          const float* __restrict__ eps_arr) {
    int tid = threadIdx.x;
    int gid = blockIdx.x * FA_THREADS + tid;
    int is64 = g_is64;
    // phase 1: fill CSR srcs
    for (int e = gid; e < N_EDGES; e += FA_BLOCKS * FA_THREADS) {
        int src = (int)load_idx(edge, e, is64);
        int dst = (int)load_idx(edge, (long long)N_EDGES + e, is64);
        int pos = atomicAdd(&g_cursor[dst], 1);
        g_srcs[pos] = src;
    }
    // grid barrier (g_gbar is 0 at entry: zero-init at load, reset by k_pool)
    __syncthreads();
    if (tid == 0) {
        __threadfence();
        atomicAdd((int*)&g_gbar, 1);
        while (g_gbar < FA_BLOCKS) { }
    }
    __syncthreads();
    __threadfence();
    // phase 2: layer-0 aggregation
    float eps = 1.0f + eps_arr[0];
    const float4* x4 = (const float4*)xin;
    int gw = gid >> 5, lane = tid & 31;
    const int NW = (FA_BLOCKS * FA_THREADS) / 32;   // 4736 warps
    for (int w = gw; w < N_NODES; w += NW)
        agg_node<4>(x4, w, lane, eps, oh, ol);
}

// ---------------- standalone aggregation (layers 1-3) ----------------
__global__ void k_agg(const float* __restrict__ xin,
                      __nv_bfloat16* __restrict__ oh, __nv_bfloat16* __restrict__ ol,
                      const float* __restrict__ eps_arr, int layer) {
    int w = (blockIdx.x * blockDim.x + threadIdx.x) >> 5;
    int lane = threadIdx.x & 31;
    if (w >= N_NODES) return;
    float eps = 1.0f + eps_arr[layer];
    agg_node<8>((const float4*)xin, w, lane, eps, oh, ol);
}

// ---------------- persistent HMMA GEMM: 512 threads, warp tile m16n64 ----------------
// 16 warps (4/SMSP) double latency hiding vs the 8-warp config (occ was 12.5%,
// issue 17% — warp-starved). Warp wid: wr=wid&7 (16-row strip), wc=wid>>3
// (64-col half). Combo-major MMA order; bias/BN constants loaded per tile in
// the epilogue (not hoisted) to stay under 128 regs.

#define ASTR_B 272                      // padded row stride in bytes (136 bf16)
#define MAT_B (128 * ASTR_B)            // 34816 B per 128x128 matrix
#define SM_WH 0
#define SM_WL MAT_B
#define SM_ABUF(i) (2 * MAT_B + (i) * (2 * MAT_B))   // Ah then Al inside each buffer
#define SM_TOTAL (6 * MAT_B)            // 208896 B -> 1 CTA/SM

__device__ __forceinline__ void ldsm4(unsigned* r, unsigned addr) {
    asm volatile("ldmatrix.sync.aligned.m8n8.x4.shared.b16 {%0,%1,%2,%3}, [%4];"
                 : "=r"(r[0]), "=r"(r[1]), "=r"(r[2]), "=r"(r[3]) : "r"(addr));
}
__device__ __forceinline__ void mma_bf16(float* d, const unsigned* a, const unsigned* b) {
    asm volatile("mma.sync.aligned.m16n8k16.row.col.f32.bf16.bf16.f32 "
                 "{%0,%1,%2,%3}, {%4,%5,%6,%7}, {%8,%9}, {%0,%1,%2,%3};"
                 : "+f"(d[0]), "+f"(d[1]), "+f"(d[2]), "+f"(d[3])
                 : "r"(a[0]), "r"(a[1]), "r"(a[2]), "r"(a[3]), "r"(b[0]), "r"(b[1]));
}
__device__ __forceinline__ void cp16(unsigned saddr, const void* g, int nbytes) {
    asm volatile("cp.async.cg.shared.global [%0], [%1], 16, %2;"
                 :: "r"(saddr), "l"(g), "r"(nbytes) : "memory");
}

// issue cp.asyncs for one 128x128 bf16 A tile (hi+lo) into buffer at sbuf
__device__ __forceinline__ void issue_A(const __nv_bfloat16* __restrict__ Ah,
                                        const __nv_bfloat16* __restrict__ Al,
                                        int row0, unsigned sbuf, int tid) {
    #pragma unroll
    for (int it = 0; it < 4; it++) {
        int i = tid + it * MMA_THREADS;          // 0..2047 16B chunks
        int r = i >> 4, c16 = i & 15;
        bool ok = (row0 + r) < N_NODES;
        const char* gh = (const char*)(Ah + (long long)(row0 + r) * 128) + c16 * 16;
        const char* gl = (const char*)(Al + (long long)(row0 + r) * 128) + c16 * 16;
        unsigned d = sbuf + (unsigned)(r * ASTR_B + c16 * 16);
        cp16(d, ok ? gh : (const char*)Ah, ok ? 16 : 0);
        cp16(d + MAT_B, ok ? gl : (const char*)Al, ok ? 16 : 0);
    }
}

__global__ void __launch_bounds__(MMA_THREADS, 1)
k_mma(const __nv_bfloat16* __restrict__ Ah, const __nv_bfloat16* __restrict__ Al,
      const __nv_bfloat16* __restrict__ Wh, const __nv_bfloat16* __restrict__ Wl,
      const float* __restrict__ bias,
      float* __restrict__ outf,
      __nv_bfloat16* __restrict__ outh, __nv_bfloat16* __restrict__ outl,
      const float* __restrict__ gamma, const float* __restrict__ beta,
      const float* __restrict__ mean,  const float* __restrict__ var) {
    extern __shared__ char smem[];
    unsigned sb;
    asm("{ .reg .u64 t; cvta.to.shared.u64 t, %1; cvt.u32.u64 %0, t; }" : "=r"(sb) : "l"(smem));
    int tid = threadIdx.x, wid = tid >> 5, lane = tid & 31;

    // stage W hi/lo once + prefetch first A tile (single commit group)
    #pragma unroll
    for (int it = 0; it < 4; it++) {
        int i = tid + it * MMA_THREADS;
        int r = i >> 4, c16 = i & 15;
        unsigned off = (unsigned)(r * ASTR_B + c16 * 16);
        cp16(sb + SM_WH + off, (const char*)(Wh + (long long)r * 128) + c16 * 16, 16);
        cp16(sb + SM_WL + off, (const char*)(Wl + (long long)r * 128) + c16 * 16, 16);
    }
    int tile = blockIdx.x;
    if (tile < MTILES) issue_A(Ah, Al, tile * 128, sb + SM_ABUF(0), tid);
    asm volatile("cp.async.commit_group;" ::: "memory");

    int wr = wid & 7, wc = wid >> 3;      // warp tile: rows wr*16..+16, cols wc*64..+64
    int quad = lane >> 2, qi = lane & 3;

    // ldmatrix lane address components
    // A: m16 strip -> x4 covers (16 rows) x (2 k-halves)
    unsigned aoff = (unsigned)((wr * 16 + (lane & 15)) * ASTR_B + (lane >> 4) * 16);
    // B x4 covers nt-pair: m = lane>>3: m0=(nt,k0), m1=(nt,k1), m2=(nt+1,k0), m3=(nt+1,k1)
    int bm = lane >> 3;
    int b_nt_off = bm >> 1;
    int b_kh = bm & 1;
    unsigned boff = (unsigned)((wc * 64 + b_nt_off * 8 + (lane & 7)) * ASTR_B + b_kh * 16);
    unsigned bH = sb + SM_WH + boff, bL = sb + SM_WL + boff;

    bool bn = (gamma != nullptr);
    int bufi = 0;
    for (; tile < MTILES; tile += PERSIST_GRID, bufi ^= 1) {
        asm volatile("cp.async.wait_group 0;" ::: "memory");
        __syncthreads();
        int next = tile + PERSIST_GRID;
        if (next < MTILES) issue_A(Ah, Al, next * 128, sb + SM_ABUF(bufi ^ 1), tid);
        asm volatile("cp.async.commit_group;" ::: "memory");

        unsigned abase = sb + SM_ABUF(bufi);
        unsigned aH0 = abase + aoff;
        unsigned aL0 = abase + MAT_B + aoff;

        float acc[8][4];
        #pragma unroll
        for (int nt = 0; nt < 8; nt++)
            #pragma unroll
            for (int j = 0; j < 4; j++) acc[nt][j] = 0.f;

        #pragma unroll
        for (int ks = 0; ks < 8; ks++) {
            unsigned kb = (unsigned)(ks * 32);            // k0 * 2 bytes
            unsigned ah[4], al[4], bhr[4][4], blr[4][4];
            ldsm4(ah, aH0 + kb);
            ldsm4(al, aL0 + kb);
            #pragma unroll
            for (int np = 0; np < 4; np++) {              // nt pair {2np, 2np+1}
                ldsm4(bhr[np], bH + (unsigned)(np * 16 * ASTR_B) + kb);
                ldsm4(blr[np], bL + (unsigned)(np * 16 * ASTR_B) + kb);
            }
            // combo-major: 8 independent MMAs per combo
            #pragma unroll
            for (int nt = 0; nt < 8; nt++)
                mma_bf16(acc[nt], ah, &bhr[nt >> 1][(nt & 1) * 2]);
            #pragma unroll
            for (int nt = 0; nt < 8; nt++)
                mma_bf16(acc[nt], ah, &blr[nt >> 1][(nt & 1) * 2]);
            #pragma unroll
            for (int nt = 0; nt < 8; nt++)
                mma_bf16(acc[nt], al, &bhr[nt >> 1][(nt & 1) * 2]);
        }

        // epilogue: C frag m16n8 -> rows quad, quad+8; cols qi*2, qi*2+1
        int row0 = tile * 128;
        int r0 = row0 + wr * 16 + quad;
        #pragma unroll
        for (int half = 0; half < 2; half++) {
            int r = r0 + half * 8;
            if (r >= N_NODES) continue;
            #pragma unroll
            for (int nt = 0; nt < 8; nt++) {
                int c = wc * 64 + nt * 8 + qi * 2;
                float d0 = acc[nt][half * 2], d1 = acc[nt][half * 2 + 1];
                float v0 = fmaxf(d0 + __ldg(bias + c), 0.f);
                float v1 = fmaxf(d1 + __ldg(bias + c + 1), 0.f);
                if (outf) {
                    if (bn) {
                        float s0 = __ldg(gamma + c) * rsqrtf(__ldg(var + c) + 1e-5f);
                        float s1 = __ldg(gamma + c + 1) * rsqrtf(__ldg(var + c + 1) + 1e-5f);
                        v0 = (v0 - __ldg(mean + c)) * s0 + __ldg(beta + c);
                        v1 = (v1 - __ldg(mean + c + 1)) * s1 + __ldg(beta + c + 1);
                    }
                    *(float2*)(outf + (long long)r * 128 + c) = make_float2(v0, v1);
                } else {
                    float h0 = __bfloat162float(__float2bfloat16(v0));
                    float h1 = __bfloat162float(__float2bfloat16(v1));
                    *(unsigned*)(outh + (long long)r * 128 + c) = pack_bf(h0, h1);
                    *(unsigned*)(outl + (long long)r * 128 + c) = pack_bf(v0 - h0, v1 - h1);
                }
            }
        }
    }
}

// ---------------- mean pool per graph (batch sorted) + scratch reset tail ----------------
__device__ __forceinline__ int lower_bound_batch(const void* batch, long long key, int is64) {
    int lo = 0, hi = N_NODES;
    while (lo < hi) {
        int mid = (lo + hi) >> 1;
        long long v = load_idx(batch, mid, is64);
        if (v < key) lo = mid + 1; else hi = mid;
    }
    return lo;
}

__global__ void k_pool(const float* __restrict__ x, const void* __restrict__ batch) {
    int g = blockIdx.x;
    int f = threadIdx.x;
    __shared__ int s_beg, s_end;
    if (f == 0) {
        int is64 = g_is64;
        s_beg = lower_bound_batch(batch, g, is64);
        s_end = lower_bound_batch(batch, g + 1, is64);
    }
    __syncthreads();
    int beg = s_beg, end = s_end;
    float s = 0.f;
    for (int r = beg; r < end; r++) s += x[(long long)r * HID + f];
    float cnt = (float)(end - beg);
    g_pooled[g * HID + f] = s / fmaxf(cnt, 1.0f);

    // tail: reset CSR scratch + barriers for the next graph replay
    int gt = g * HID + f;
    for (int i = gt; i < N_NODES + 1; i += N_GRAPHS * HID) g_rowoff[i] = 0;
    if (gt < SCAN_B) g_bflag[gt] = 0;
    if (gt == 0) g_gbar = 0;
}

// ---------------- head: relu(pooled@W1+b1) @ W2 + b2, log_softmax ----------------
__global__ void k_head(const float* __restrict__ W1, const float* __restrict__ b1,
                       const float* __restrict__ W2, const float* __restrict__ b2,
                       float* __restrict__ out) {
    int g = blockIdx.x;
    int t = threadIdx.x;
    __shared__ float sp[HID], sh[HID], sl[OUT_DIM];
    __shared__ float smax, slse;
    sp[t] = g_pooled[g * HID + t];
    __syncthreads();
    float acc = b1[t];
    #pragma unroll 8
    for (int k = 0; k < HID; k++) acc += sp[k] * W1[k * HID + t];
    sh[t] = fmaxf(acc, 0.f);
    __syncthreads();
    if (t < OUT_DIM) {
        float a = b2[t];
        #pragma unroll 8
        for (int k = 0; k < HID; k++) a += sh[k] * W2[k * OUT_DIM + t];
        sl[t] = a;
    }
    __syncthreads();
    if (t == 0) {
        float m = -1e30f;
        for (int o = 0; o < OUT_DIM; o++) m = fmaxf(m, sl[o]);
        float s = 0.f;
        for (int o = 0; o < OUT_DIM; o++) s += expf(sl[o] - m);
        smax = m; slse = logf(s);
    }
    __syncthreads();
    if (t < OUT_DIM) out[g * OUT_DIM + t] = sl[t] - smax - slse;
}

// ---------------- launch ----------------
extern "C" void kernel_launch(void* const* d_in, const int* in_sizes, int n_in,
                              void* d_out, int out_size) {
    const float* x      = (const float*)d_in[0];
    const void*  edge   = d_in[1];
    const void*  batch  = d_in[2];
    const float* W1s    = (const float*)d_in[3];
    const float* b1s    = (const float*)d_in[4];
    const float* W2s    = (const float*)d_in[5];
    const float* b2s    = (const float*)d_in[6];
    const float* gammas = (const float*)d_in[7];
    const float* betas  = (const float*)d_in[8];
    const float* means  = (const float*)d_in[9];
    const float* vars   = (const float*)d_in[10];
    const float* epsarr = (const float*)d_in[11];
    const float* lin1W  = (const float*)d_in[12];
    const float* lin1b  = (const float*)d_in[13];
    const float* lin2W  = (const float*)d_in[14];
    const float* lin2b  = (const float*)d_in[15];
    float* out = (float*)d_out;

    float *A;
    __nv_bfloat16 *Bh, *Bl, *Ch, *Cl, *Wth, *Wtl;
    cudaGetSymbolAddress((void**)&A,  g_A);
    cudaGetSymbolAddress((void**)&Bh, g_Bh);
    cudaGetSymbolAddress((void**)&Bl, g_Bl);
    cudaGetSymbolAddress((void**)&Ch, g_Ch);
    cudaGetSymbolAddress((void**)&Cl, g_Cl);
    cudaGetSymbolAddress((void**)&Wth, g_Wth);
    cudaGetSymbolAddress((void**)&Wtl, g_Wtl);

    cudaFuncSetAttribute(k_mma, cudaFuncAttributeMaxDynamicSharedMemorySize, SM_TOTAL);

    // CSR build + weight prep; fillagg fuses fill with layer-0 agg so that
    // k_mma is launch #4 (the ncu capture slot)
    k_count<<<EDGE_BLOCKS + WPREP_BLOCKS, 256>>>(edge, W1s, W2s);
    k_scanall<<<SCAN_B, 1024>>>();
    k_fillagg<<<FA_BLOCKS, FA_THREADS>>>(edge, x, Bh, Bl, epsarr);

    const int agg_blocks = (N_NODES * 32 + 255) / 256;

    for (int l = 0; l < N_LAYERS; l++) {
        if (l > 0)
            k_agg<<<agg_blocks, 256>>>(A, Bh, Bl, epsarr, l);
        // GEMM1: relu -> bf16 hi/lo
        k_mma<<<PERSIST_GRID, MMA_THREADS, SM_TOTAL>>>(
            Bh, Bl, Wth + (l * 2) * 16384, Wtl + (l * 2) * 16384,
            b1s + l * HID, nullptr, Ch, Cl,
            nullptr, nullptr, nullptr, nullptr);
        // GEMM2: relu + BN -> fp32
        k_mma<<<PERSIST_GRID, MMA_THREADS, SM_TOTAL>>>(
            Ch, Cl, Wth + (l * 2 + 1) * 16384, Wtl + (l * 2 + 1) * 16384,
            b2s + l * HID, A, nullptr, nullptr,
            gammas + l * HID, betas + l * HID, means + l * HID, vars + l * HID);
    }

    k_pool<<<N_GRAPHS, HID>>>(A, batch);
    k_head<<<N_GRAPHS, HID>>>(lin1W, lin1b, lin2W, lin2b, out);
}

// round 14
// speedup vs baseline: 1.3368x; 1.3368x over previous
#include <cuda_runtime.h>
#include <cuda_bf16.h>
#include <stdint.h>
#include <math.h>

#define N_NODES 50000
#define N_EDGES 800000
#define HID     128
#define OUT_DIM 40
#define N_LAYERS 4
#define N_GRAPHS 128
#define SCAN_B  49           // ceil(50000/1024)
#define EDGE_BLOCKS 3125     // ceil(800000/256)
#define WPREP_ELEMS (8 * HID * HID)
#define WPREP_BLOCKS ((WPREP_ELEMS + 255) / 256)
#define MTILES ((N_NODES + 127) / 128)     // 391
#define PERSIST_GRID 148                   // one wave, 1 CTA/SM
#define FA_BLOCKS 148
#define FA_THREADS 1024

// ---------------- scratch (static device globals; zero-initialized at load) ----------------
__device__ float g_A[N_NODES * HID];                    // fp32 node features (layer output)
__device__ __nv_bfloat16 g_Bh[N_NODES * HID];           // agg output hi  (layer input)
__device__ __nv_bfloat16 g_Bl[N_NODES * HID];           // agg output lo
__device__ __nv_bfloat16 g_Wth[WPREP_ELEMS];            // transposed weights hi: [mat][n][k]
__device__ __nv_bfloat16 g_Wtl[WPREP_ELEMS];            // transposed weights lo
__device__ int   g_rowoff[N_NODES + 1];                 // zeroed at load + k_pool tail
__device__ int   g_cursor[N_NODES];
__device__ int   g_srcs[N_EDGES];
__device__ volatile int g_bsum[SCAN_B];
__device__ volatile int g_bflag[SCAN_B];                // zeroed at load + k_pool tail
__device__ volatile int g_gbar;                         // fillagg grid barrier; reset in k_pool
__device__ int   g_is64;
__device__ float g_pooled[N_GRAPHS * HID];

// ---------------- helpers ----------------
__device__ __forceinline__ long long load_idx(const void* p, long long i, int is64) {
    if (is64) return ((const long long*)p)[i];
    return (long long)((const int*)p)[i];
}

__device__ __forceinline__ unsigned pack_bf(float a, float b) {
    __nv_bfloat162 t = __floats2bfloat162_rn(a, b);
    return *reinterpret_cast<unsigned*>(&t);
}

// ---------------- CSR count (by dst) + weight split/transpose (extra blocks) ----------------
__global__ void k_count(const void* __restrict__ edge,
                        const float* __restrict__ W1s, const float* __restrict__ W2s) {
    int b = blockIdx.x;
    if (b >= EDGE_BLOCKS) {
        // weight prep: Wt[mat][n][k] = W[mat][k][n] split into bf16 hi/lo
        int t = (b - EDGE_BLOCKS) * 256 + threadIdx.x;
        if (t < WPREP_ELEMS) {
            int mat = t >> 14, rem = t & 16383;
            int n = rem >> 7, k = rem & 127;
            int l = mat >> 1;
            float w = (mat & 1) ? W2s[l * 16384 + k * 128 + n]
                                : W1s[l * 16384 + k * 128 + n];
            __nv_bfloat16 h = __float2bfloat16(w);
            g_Wth[t] = h;
            g_Wtl[t] = __float2bfloat16(w - __bfloat162float(h));
        }
        return;
    }
    __shared__ int s_is64;
    int t = threadIdx.x;
    if (t == 0) s_is64 = 1;
    __syncthreads();
    if (t < 64) {
        // int32 data reinterpreted as int64 has a random node id in the high
        // word (invalid w.p. ~1), so 64 valid samples => genuine int64.
        long long v = ((const long long*)edge)[(long long)t * 12347 + 5];
        if (v < 0 || v >= N_NODES) atomicAnd(&s_is64, 0);
    }
    __syncthreads();
    int is64 = s_is64;
    if (b == 0 && t == 0) g_is64 = is64;
    int e = b * blockDim.x + t;
    if (e < N_EDGES) {
        int dst = (int)load_idx(edge, (long long)N_EDGES + e, is64);
        atomicAdd(&g_rowoff[dst], 1);
    }
}

// ---------------- single-kernel scan: block scan + decoupled lookback ----------------
__global__ void k_scanall() {
    __shared__ int part[1024];
    __shared__ int s_pref;
    int t = threadIdx.x, bid = blockIdx.x;
    int idx = bid * 1024 + t;
    int c = (idx < N_NODES) ? g_rowoff[idx] : 0;
    part[t] = c;
    __syncthreads();
    #pragma unroll
    for (int off = 1; off < 1024; off <<= 1) {
        int v = (t >= off) ? part[t - off] : 0;
        __syncthreads();
        part[t] += v;
        __syncthreads();
    }
    if (t == 1023) {
        g_bsum[bid] = part[1023];
        __threadfence();
        g_bflag[bid] = 1;
    }
    if (t < 32) {
        int s = 0;
        for (int p = t; p < bid; p += 32) {
            while (g_bflag[p] == 0) { }
            s += g_bsum[p];
        }
        #pragma unroll
        for (int o = 16; o; o >>= 1) s += __shfl_xor_sync(0xffffffffu, s, o);
        if (t == 0) s_pref = s;
    }
    __syncthreads();
    int pref = s_pref;
    if (idx < N_NODES) {
        int v = pref + part[t] - c;
        g_rowoff[idx] = v;
        g_cursor[idx] = v;
    }
    if (bid == SCAN_B - 1 && t == 1023) g_rowoff[N_NODES] = N_EDGES;
}

// ---------------- shared aggregation body ----------------
template <int U>
__device__ __forceinline__ void agg_node(const float4* __restrict__ x4, int w, int lane,
                                         float eps,
                                         __nv_bfloat16* __restrict__ oh,
                                         __nv_bfloat16* __restrict__ ol) {
    float4 a = x4[(long long)w * 32 + lane];
    float ax = a.x * eps, ay = a.y * eps, az = a.z * eps, aw = a.w * eps;
    int e = g_rowoff[w], end = g_rowoff[w + 1];
    for (; e + U - 1 < end; e += U) {
        int ss[U];
        float4 vv[U];
        #pragma unroll
        for (int j = 0; j < U; j++) ss[j] = g_srcs[e + j];
        #pragma unroll
        for (int j = 0; j < U; j++) vv[j] = x4[(long long)ss[j] * 32 + lane];
        #pragma unroll
        for (int j = 0; j < U; j++) {
            ax += vv[j].x; ay += vv[j].y; az += vv[j].z; aw += vv[j].w;
        }
    }
    for (; e < end; e++) {
        int s = g_srcs[e];
        float4 v = x4[(long long)s * 32 + lane];
        ax += v.x; ay += v.y; az += v.z; aw += v.w;
    }
    float hx = __bfloat162float(__float2bfloat16(ax));
    float hy = __bfloat162float(__float2bfloat16(ay));
    float hz = __bfloat162float(__float2bfloat16(az));
    float hw = __bfloat162float(__float2bfloat16(aw));
    uint2 H = make_uint2(pack_bf(hx, hy), pack_bf(hz, hw));
    uint2 L = make_uint2(pack_bf(ax - hx, ay - hy), pack_bf(az - hz, aw - hw));
    *(uint2*)(oh + (long long)w * 128 + lane * 4) = H;
    *(uint2*)(ol + (long long)w * 128 + lane * 4) = L;
}

// ---------------- fused CSR-fill + layer-0 aggregation (persistent, grid barrier) ----------------
__global__ void __launch_bounds__(FA_THREADS, 1)
k_fillagg(const void* __restrict__ edge, const float* __restrict__ xin,
          __nv_bfloat16* __restrict__ oh, __nv_bfloat16* __restrict__ ol,
          const float* __restrict__ eps_arr) {
    int tid = threadIdx.x;
    int gid = blockIdx.x * FA_THREADS + tid;
    int is64 = g_is64;
    for (int e = gid; e < N_EDGES; e += FA_BLOCKS * FA_THREADS) {
        int src = (int)load_idx(edge, e, is64);
        int dst = (int)load_idx(edge, (long long)N_EDGES + e, is64);
        int pos = atomicAdd(&g_cursor[dst], 1);
        g_srcs[pos] = src;
    }
    __syncthreads();
    if (tid == 0) {
        __threadfence();
        atomicAdd((int*)&g_gbar, 1);
        while (g_gbar < FA_BLOCKS) { }
    }
    __syncthreads();
    __threadfence();
    float eps = 1.0f + eps_arr[0];
    const float4* x4 = (const float4*)xin;
    int gw = gid >> 5, lane = tid & 31;
    const int NW = (FA_BLOCKS * FA_THREADS) / 32;
    for (int w = gw; w < N_NODES; w += NW)
        agg_node<4>(x4, w, lane, eps, oh, ol);
}

// ---------------- standalone aggregation (layers 1-3) ----------------
__global__ void k_agg(const float* __restrict__ xin,
                      __nv_bfloat16* __restrict__ oh, __nv_bfloat16* __restrict__ ol,
                      const float* __restrict__ eps_arr, int layer) {
    int w = (blockIdx.x * blockDim.x + threadIdx.x) >> 5;
    int lane = threadIdx.x & 31;
    if (w >= N_NODES) return;
    float eps = 1.0f + eps_arr[layer];
    agg_node<8>((const float4*)xin, w, lane, eps, oh, ol);
}

// ---------------- fused per-layer GEMM pair (persistent HMMA, R12 mainloop) ----------------
// Per tile: T1 = relu(A@W1t^T + b1) computed in regs, hi/lo-split back into the
// A smem buffer, then OUT = BN(relu(T1@W2t^T + b2)) -> fp32. W1/W2 hi/lo staged
// once per CTA. Combo-major MMA order (AhWh, AhWl, AlWh).

#define ASTR_B 272                      // padded row stride in bytes (136 bf16)
#define MAT_B (128 * ASTR_B)            // 34816 B per 128x128 matrix
#define SM_W1H 0
#define SM_W1L MAT_B
#define SM_W2H (2 * MAT_B)
#define SM_W2L (3 * MAT_B)
#define SM_AH  (4 * MAT_B)
#define SM_AL  (5 * MAT_B)
#define SM_TOTAL (6 * MAT_B)            // 208896 B -> 1 CTA/SM

__device__ __forceinline__ void ldsm4(unsigned* r, unsigned addr) {
    asm volatile("ldmatrix.sync.aligned.m8n8.x4.shared.b16 {%0,%1,%2,%3}, [%4];"
                 : "=r"(r[0]), "=r"(r[1]), "=r"(r[2]), "=r"(r[3]) : "r"(addr));
}
__device__ __forceinline__ void mma_bf16(float* d, const unsigned* a, const unsigned* b) {
    asm volatile("mma.sync.aligned.m16n8k16.row.col.f32.bf16.bf16.f32 "
                 "{%0,%1,%2,%3}, {%4,%5,%6,%7}, {%8,%9}, {%0,%1,%2,%3};"
                 : "+f"(d[0]), "+f"(d[1]), "+f"(d[2]), "+f"(d[3])
                 : "r"(a[0]), "r"(a[1]), "r"(a[2]), "r"(a[3]), "r"(b[0]), "r"(b[1]));
}
__device__ __forceinline__ void cp16(unsigned saddr, const void* g, int nbytes) {
    asm volatile("cp.async.cg.shared.global [%0], [%1], 16, %2;"
                 :: "r"(saddr), "l"(g), "r"(nbytes) : "memory");
}

// issue cp.asyncs for one 128x128 bf16 A tile (hi+lo) into SM_AH/SM_AL
__device__ __forceinline__ void issue_A(const __nv_bfloat16* __restrict__ Ah,
                                        const __nv_bfloat16* __restrict__ Al,
                                        int row0, unsigned sb, int tid) {
    #pragma unroll
    for (int it = 0; it < 8; it++) {
        int i = tid + it * 256;                  // 0..2047 16B chunks
        int r = i >> 4, c16 = i & 15;
        bool ok = (row0 + r) < N_NODES;
        const char* gh = (const char*)(Ah + (long long)(row0 + r) * 128) + c16 * 16;
        const char* gl = (const char*)(Al + (long long)(row0 + r) * 128) + c16 * 16;
        unsigned d = sb + SM_AH + (unsigned)(r * ASTR_B + c16 * 16);
        cp16(d, ok ? gh : (const char*)Ah, ok ? 16 : 0);
        cp16(d + MAT_B, ok ? gl : (const char*)Al, ok ? 16 : 0);
    }
}

// one 128x128 GEMM mainloop (R12 combo-major), acc += (Ah+Al)@(Wh+Wl) approx
__device__ __forceinline__ void gemm_tile(unsigned aH0, unsigned aL0,
                                          unsigned bH, unsigned bL,
                                          float acc[2][8][4]) {
    unsigned aH1 = aH0 + 16 * ASTR_B, aL1 = aL0 + 16 * ASTR_B;
    #pragma unroll
    for (int ks = 0; ks < 8; ks++) {
        unsigned kb = (unsigned)(ks * 32);
        unsigned ah[2][4], al[2][4], bhr[4][4], blr[4][4];
        ldsm4(ah[0], aH0 + kb);
        ldsm4(ah[1], aH1 + kb);
        ldsm4(al[0], aL0 + kb);
        ldsm4(al[1], aL1 + kb);
        #pragma unroll
        for (int np = 0; np < 4; np++) {
            ldsm4(bhr[np], bH + (unsigned)(np * 16 * ASTR_B) + kb);
            ldsm4(blr[np], bL + (unsigned)(np * 16 * ASTR_B) + kb);
        }
        #pragma unroll
        for (int mt = 0; mt < 2; mt++)
            #pragma unroll
            for (int nt = 0; nt < 8; nt++)
                mma_bf16(acc[mt][nt], ah[mt], &bhr[nt >> 1][(nt & 1) * 2]);
        #pragma unroll
        for (int mt = 0; mt < 2; mt++)
            #pragma unroll
            for (int nt = 0; nt < 8; nt++)
                mma_bf16(acc[mt][nt], ah[mt], &blr[nt >> 1][(nt & 1) * 2]);
        #pragma unroll
        for (int mt = 0; mt < 2; mt++)
            #pragma unroll
            for (int nt = 0; nt < 8; nt++)
                mma_bf16(acc[mt][nt], al[mt], &bhr[nt >> 1][(nt & 1) * 2]);
    }
}

__global__ void __launch_bounds__(256, 1)
k_layer(const __nv_bfloat16* __restrict__ Ah, const __nv_bfloat16* __restrict__ Al,
        const __nv_bfloat16* __restrict__ W1h, const __nv_bfloat16* __restrict__ W1l,
        const __nv_bfloat16* __restrict__ W2h, const __nv_bfloat16* __restrict__ W2l,
        const float* __restrict__ b1, const float* __restrict__ b2,
        float* __restrict__ outf,
        const float* __restrict__ gamma, const float* __restrict__ beta,
        const float* __restrict__ mean,  const float* __restrict__ var) {
    extern __shared__ char smem[];
    unsigned sb;
    asm("{ .reg .u64 t; cvta.to.shared.u64 t, %1; cvt.u32.u64 %0, t; }" : "=r"(sb) : "l"(smem));
    int tid = threadIdx.x, wid = tid >> 5, lane = tid & 31;

    // stage 4 W matrices once + first A tile (single commit group)
    #pragma unroll
    for (int it = 0; it < 32; it++) {
        int i = tid + it * 256;                  // 0..8191 16B chunks
        int m = i >> 11;                         // matrix 0..3
        int j = i & 2047;
        int r = j >> 4, c16 = j & 15;
        const __nv_bfloat16* src = (m == 0) ? W1h : (m == 1) ? W1l : (m == 2) ? W2h : W2l;
        cp16(sb + (unsigned)(m * MAT_B + r * ASTR_B + c16 * 16),
             (const char*)(src + (long long)r * 128) + c16 * 16, 16);
    }
    int tile = blockIdx.x;
    if (tile < MTILES) issue_A(Ah, Al, tile * 128, sb, tid);
    asm volatile("cp.async.commit_group;" ::: "memory");

    int wr = wid & 3, wc = wid >> 2;      // warp tile: rows wr*32..+32, cols wc*64..+64
    int quad = lane >> 2, qi = lane & 3;

    // ldmatrix lane address components
    unsigned aoff = (unsigned)((wr * 32 + (lane & 15)) * ASTR_B + (lane >> 4) * 16);
    int bm = lane >> 3;
    int b_nt_off = bm >> 1;
    int b_kh = bm & 1;
    unsigned boff = (unsigned)((wc * 64 + b_nt_off * 8 + (lane & 7)) * ASTR_B + b_kh * 16);
    unsigned b1H = sb + SM_W1H + boff, b1L = sb + SM_W1L + boff;
    unsigned b2H = sb + SM_W2H + boff, b2L = sb + SM_W2L + boff;
    unsigned aH0 = sb + SM_AH + aoff, aL0 = sb + SM_AL + aoff;

    for (; tile < MTILES; tile += PERSIST_GRID) {
        asm volatile("cp.async.wait_group 0;" ::: "memory");
        __syncthreads();

        // ---- GEMM1: acc = A @ W1t^T ----
        float acc[2][8][4];
        #pragma unroll
        for (int mt = 0; mt < 2; mt++)
            #pragma unroll
            for (int nt = 0; nt < 8; nt++)
                #pragma unroll
                for (int j = 0; j < 4; j++) acc[mt][nt][j] = 0.f;
        gemm_tile(aH0, aL0, b1H, b1L, acc);
        __syncthreads();   // all warps done reading A before overwrite

        // ---- T1 = relu(acc + b1), hi/lo split, store into A buffer ----
        #pragma unroll
        for (int mt = 0; mt < 2; mt++) {
            int rr = wr * 32 + mt * 16 + quad;       // smem row (always valid)
            #pragma unroll
            for (int half = 0; half < 2; half++) {
                int r = rr + half * 8;
                #pragma unroll
                for (int nt = 0; nt < 8; nt++) {
                    int c = wc * 64 + nt * 8 + qi * 2;
                    float v0 = fmaxf(acc[mt][nt][half * 2] + __ldg(b1 + c), 0.f);
                    float v1 = fmaxf(acc[mt][nt][half * 2 + 1] + __ldg(b1 + c + 1), 0.f);
                    float h0 = __bfloat162float(__float2bfloat16(v0));
                    float h1 = __bfloat162float(__float2bfloat16(v1));
                    unsigned soff = (unsigned)(r * ASTR_B + c * 2);
                    *(unsigned*)(smem + SM_AH + soff) = pack_bf(h0, h1);
                    *(unsigned*)(smem + SM_AL + soff) = pack_bf(v0 - h0, v1 - h1);
                }
            }
        }
        __syncthreads();

        // ---- GEMM2: acc = T1 @ W2t^T ----
        #pragma unroll
        for (int mt = 0; mt < 2; mt++)
            #pragma unroll
            for (int nt = 0; nt < 8; nt++)
                #pragma unroll
                for (int j = 0; j < 4; j++) acc[mt][nt][j] = 0.f;
        gemm_tile(aH0, aL0, b2H, b2L, acc);
        __syncthreads();   // done reading T1; buffer free for next prefetch

        int next = tile + PERSIST_GRID;
        if (next < MTILES) issue_A(Ah, Al, next * 128, sb, tid);
        asm volatile("cp.async.commit_group;" ::: "memory");

        // ---- epilogue: BN(relu(acc + b2)) -> fp32 out ----
        int row0 = tile * 128;
        #pragma unroll
        for (int mt = 0; mt < 2; mt++) {
            int r0 = row0 + wr * 32 + mt * 16 + quad;
            #pragma unroll
            for (int half = 0; half < 2; half++) {
                int r = r0 + half * 8;
                if (r >= N_NODES) continue;
                #pragma unroll
                for (int nt = 0; nt < 8; nt++) {
                    int c = wc * 64 + nt * 8 + qi * 2;
                    float v0 = fmaxf(acc[mt][nt][half * 2] + __ldg(b2 + c), 0.f);
                    float v1 = fmaxf(acc[mt][nt][half * 2 + 1] + __ldg(b2 + c + 1), 0.f);
                    float s0 = __ldg(gamma + c) * rsqrtf(__ldg(var + c) + 1e-5f);
                    float s1 = __ldg(gamma + c + 1) * rsqrtf(__ldg(var + c + 1) + 1e-5f);
                    v0 = (v0 - __ldg(mean + c)) * s0 + __ldg(beta + c);
                    v1 = (v1 - __ldg(mean + c + 1)) * s1 + __ldg(beta + c + 1);
                    *(float2*)(outf + (long long)r * 128 + c) = make_float2(v0, v1);
                }
            }
        }
    }
}

// ---------------- mean pool per graph (batch sorted) + scratch reset tail ----------------
__device__ __forceinline__ int lower_bound_batch(const void* batch, long long key, int is64) {
    int lo = 0, hi = N_NODES;
    while (lo < hi) {
        int mid = (lo + hi) >> 1;
        long long v = load_idx(batch, mid, is64);
        if (v < key) lo = mid + 1; else hi = mid;
    }
    return lo;
}

__global__ void k_pool(const float* __restrict__ x, const void* __restrict__ batch) {
    int g = blockIdx.x;
    int f = threadIdx.x;
    __shared__ int s_beg, s_end;
    if (f == 0) {
        int is64 = g_is64;
        s_beg = lower_bound_batch(batch, g, is64);
        s_end = lower_bound_batch(batch, g + 1, is64);
    }
    __syncthreads();
    int beg = s_beg, end = s_end;
    float s = 0.f;
    for (int r = beg; r < end; r++) s += x[(long long)r * HID + f];
    float cnt = (float)(end - beg);
    g_pooled[g * HID + f] = s / fmaxf(cnt, 1.0f);

    // tail: reset CSR scratch + barriers for the next graph replay
    int gt = g * HID + f;
    for (int i = gt; i < N_NODES + 1; i += N_GRAPHS * HID) g_rowoff[i] = 0;
    if (gt < SCAN_B) g_bflag[gt] = 0;
    if (gt == 0) g_gbar = 0;
}

// ---------------- head: relu(pooled@W1+b1) @ W2 + b2, log_softmax ----------------
__global__ void k_head(const float* __restrict__ W1, const float* __restrict__ b1,
                       const float* __restrict__ W2, const float* __restrict__ b2,
                       float* __restrict__ out) {
    int g = blockIdx.x;
    int t = threadIdx.x;
    __shared__ float sp[HID], sh[HID], sl[OUT_DIM];
    __shared__ float smax, slse;
    sp[t] = g_pooled[g * HID + t];
    __syncthreads();
    float acc = b1[t];
    #pragma unroll 8
    for (int k = 0; k < HID; k++) acc += sp[k] * W1[k * HID + t];
    sh[t] = fmaxf(acc, 0.f);
    __syncthreads();
    if (t < OUT_DIM) {
        float a = b2[t];
        #pragma unroll 8
        for (int k = 0; k < HID; k++) a += sh[k] * W2[k * OUT_DIM + t];
        sl[t] = a;
    }
    __syncthreads();
    if (t == 0) {
        float m = -1e30f;
        for (int o = 0; o < OUT_DIM; o++) m = fmaxf(m, sl[o]);
        float s = 0.f;
        for (int o = 0; o < OUT_DIM; o++) s += expf(sl[o] - m);
        smax = m; slse = logf(s);
    }
    __syncthreads();
    if (t < OUT_DIM) out[g * OUT_DIM + t] = sl[t] - smax - slse;
}

// ---------------- launch ----------------
extern "C" void kernel_launch(void* const* d_in, const int* in_sizes, int n_in,
                              void* d_out, int out_size) {
    const float* x      = (const float*)d_in[0];
    const void*  edge   = d_in[1];
    const void*  batch  = d_in[2];
    const float* W1s    = (const float*)d_in[3];
    const float* b1s    = (const float*)d_in[4];
    const float* W2s    = (const float*)d_in[5];
    const float* b2s    = (const float*)d_in[6];
    const float* gammas = (const float*)d_in[7];
    const float* betas  = (const float*)d_in[8];
    const float* means  = (const float*)d_in[9];
    const float* vars   = (const float*)d_in[10];
    const float* epsarr = (const float*)d_in[11];
    const float* lin1W  = (const float*)d_in[12];
    const float* lin1b  = (const float*)d_in[13];
    const float* lin2W  = (const float*)d_in[14];
    const float* lin2b  = (const float*)d_in[15];
    float* out = (float*)d_out;

    float *A;
    __nv_bfloat16 *Bh, *Bl, *Wth, *Wtl;
    cudaGetSymbolAddress((void**)&A,  g_A);
    cudaGetSymbolAddress((void**)&Bh, g_Bh);
    cudaGetSymbolAddress((void**)&Bl, g_Bl);
    cudaGetSymbolAddress((void**)&Wth, g_Wth);
    cudaGetSymbolAddress((void**)&Wtl, g_Wtl);

    cudaFuncSetAttribute(k_layer, cudaFuncAttributeMaxDynamicSharedMemorySize, SM_TOTAL);

    // CSR build + weight prep; fillagg fuses fill with layer-0 agg so that
    // k_layer is launch #4 (the ncu capture slot)
    k_count<<<EDGE_BLOCKS + WPREP_BLOCKS, 256>>>(edge, W1s, W2s);
    k_scanall<<<SCAN_B, 1024>>>();
    k_fillagg<<<FA_BLOCKS, FA_THREADS>>>(edge, x, Bh, Bl, epsarr);

    const int agg_blocks = (N_NODES * 32 + 255) / 256;

    for (int l = 0; l < N_LAYERS; l++) {
        if (l > 0)
            k_agg<<<agg_blocks, 256>>>(A, Bh, Bl, epsarr, l);
        k_layer<<<PERSIST_GRID, 256, SM_TOTAL>>>(
            Bh, Bl,
            Wth + (l * 2) * 16384, Wtl + (l * 2) * 16384,
            Wth + (l * 2 + 1) * 16384, Wtl + (l * 2 + 1) * 16384,
            b1s + l * HID, b2s + l * HID,
            A,
            gammas + l * HID, betas + l * HID, means + l * HID, vars + l * HID);
    }

    k_pool<<<N_GRAPHS, HID>>>(A, batch);
    k_head<<<N_GRAPHS, HID>>>(lin1W, lin1b, lin2W, lin2b, out);
}

// round 15
// speedup vs baseline: 1.4076x; 1.0530x over previous
#include <cuda_runtime.h>
#include <cuda_bf16.h>
#include <cuda_fp16.h>
#include <stdint.h>
#include <math.h>

#define N_NODES 50000
#define N_EDGES 800000
#define HID     128
#define OUT_DIM 40
#define N_LAYERS 4
#define N_GRAPHS 128
#define SCAN_B  49           // ceil(50000/1024)
#define EDGE_BLOCKS 3125     // ceil(800000/256)
#define WPREP_ELEMS (8 * HID * HID)
#define WPREP_BLOCKS ((WPREP_ELEMS + 255) / 256)
#define MTILES ((N_NODES + 127) / 128)     // 391
#define PERSIST_GRID 148                   // one wave, 1 CTA/SM
#define FA_BLOCKS 148
#define FA_THREADS 1024

// ---------------- scratch (static device globals; zero-initialized at load) ----------------
__device__ __half g_Ah16[N_NODES * HID];                // fp16 node features (layer output)
__device__ __nv_bfloat16 g_Bh[N_NODES * HID];           // agg output hi  (layer input)
__device__ __nv_bfloat16 g_Bl[N_NODES * HID];           // agg output lo
__device__ __nv_bfloat16 g_Wth[WPREP_ELEMS];            // transposed weights hi: [mat][n][k]
__device__ __nv_bfloat16 g_Wtl[WPREP_ELEMS];            // transposed weights lo
__device__ int   g_rowoff[N_NODES + 1];                 // zeroed at load + k_pool tail
__device__ int   g_cursor[N_NODES];
__device__ int   g_srcs[N_EDGES];
__device__ volatile int g_bsum[SCAN_B];
__device__ volatile int g_bflag[SCAN_B];                // zeroed at load + k_pool tail
__device__ volatile int g_gbar;                         // fillagg grid barrier; reset in k_pool
__device__ int   g_is64;
__device__ float g_pooled[N_GRAPHS * HID];

// ---------------- helpers ----------------
__device__ __forceinline__ long long load_idx(const void* p, long long i, int is64) {
    if (is64) return ((const long long*)p)[i];
    return (long long)((const int*)p)[i];
}

__device__ __forceinline__ unsigned pack_bf(float a, float b) {
    __nv_bfloat162 t = __floats2bfloat162_rn(a, b);
    return *reinterpret_cast<unsigned*>(&t);
}

// ---------------- CSR count (by dst) + weight split/transpose (extra blocks) ----------------
__global__ void k_count(const void* __restrict__ edge,
                        const float* __restrict__ W1s, const float* __restrict__ W2s) {
    int b = blockIdx.x;
    if (b >= EDGE_BLOCKS) {
        // weight prep: Wt[mat][n][k] = W[mat][k][n] split into bf16 hi/lo
        int t = (b - EDGE_BLOCKS) * 256 + threadIdx.x;
        if (t < WPREP_ELEMS) {
            int mat = t >> 14, rem = t & 16383;
            int n = rem >> 7, k = rem & 127;
            int l = mat >> 1;
            float w = (mat & 1) ? W2s[l * 16384 + k * 128 + n]
                                : W1s[l * 16384 + k * 128 + n];
            __nv_bfloat16 h = __float2bfloat16(w);
            g_Wth[t] = h;
            g_Wtl[t] = __float2bfloat16(w - __bfloat162float(h));
        }
        return;
    }
    __shared__ int s_is64;
    int t = threadIdx.x;
    if (t == 0) s_is64 = 1;
    __syncthreads();
    if (t < 64) {
        // int32 data reinterpreted as int64 has a random node id in the high
        // word (invalid w.p. ~1), so 64 valid samples => genuine int64.
        long long v = ((const long long*)edge)[(long long)t * 12347 + 5];
        if (v < 0 || v >= N_NODES) atomicAnd(&s_is64, 0);
    }
    __syncthreads();
    int is64 = s_is64;
    if (b == 0 && t == 0) g_is64 = is64;
    int e = b * blockDim.x + t;
    if (e < N_EDGES) {
        int dst = (int)load_idx(edge, (long long)N_EDGES + e, is64);
        atomicAdd(&g_rowoff[dst], 1);
    }
}

// ---------------- single-kernel scan: block scan + decoupled lookback ----------------
__global__ void k_scanall() {
    __shared__ int part[1024];
    __shared__ int s_pref;
    int t = threadIdx.x, bid = blockIdx.x;
    int idx = bid * 1024 + t;
    int c = (idx < N_NODES) ? g_rowoff[idx] : 0;
    part[t] = c;
    __syncthreads();
    #pragma unroll
    for (int off = 1; off < 1024; off <<= 1) {
        int v = (t >= off) ? part[t - off] : 0;
        __syncthreads();
        part[t] += v;
        __syncthreads();
    }
    if (t == 1023) {
        g_bsum[bid] = part[1023];
        __threadfence();
        g_bflag[bid] = 1;
    }
    if (t < 32) {
        int s = 0;
        for (int p = t; p < bid; p += 32) {
            while (g_bflag[p] == 0) { }
            s += g_bsum[p];
        }
        #pragma unroll
        for (int o = 16; o; o >>= 1) s += __shfl_xor_sync(0xffffffffu, s, o);
        if (t == 0) s_pref = s;
    }
    __syncthreads();
    int pref = s_pref;
    if (idx < N_NODES) {
        int v = pref + part[t] - c;
        g_rowoff[idx] = v;
        g_cursor[idx] = v;
    }
    if (bid == SCAN_B - 1 && t == 1023) g_rowoff[N_NODES] = N_EDGES;
}

// ---------------- aggregation from fp32 input (layer 0) ----------------
template <int U>
__device__ __forceinline__ void agg_node_f32(const float4* __restrict__ x4, int w, int lane,
                                             float eps,
                                             __nv_bfloat16* __restrict__ oh,
                                             __nv_bfloat16* __restrict__ ol) {
    float4 a = x4[(long long)w * 32 + lane];
    float ax = a.x * eps, ay = a.y * eps, az = a.z * eps, aw = a.w * eps;
    int e = g_rowoff[w], end = g_rowoff[w + 1];
    for (; e + U - 1 < end; e += U) {
        int ss[U];
        float4 vv[U];
        #pragma unroll
        for (int j = 0; j < U; j++) ss[j] = g_srcs[e + j];
        #pragma unroll
        for (int j = 0; j < U; j++) vv[j] = x4[(long long)ss[j] * 32 + lane];
        #pragma unroll
        for (int j = 0; j < U; j++) {
            ax += vv[j].x; ay += vv[j].y; az += vv[j].z; aw += vv[j].w;
        }
    }
    for (; e < end; e++) {
        int s = g_srcs[e];
        float4 v = x4[(long long)s * 32 + lane];
        ax += v.x; ay += v.y; az += v.z; aw += v.w;
    }
    float hx = __bfloat162float(__float2bfloat16(ax));
    float hy = __bfloat162float(__float2bfloat16(ay));
    float hz = __bfloat162float(__float2bfloat16(az));
    float hw = __bfloat162float(__float2bfloat16(aw));
    uint2 H = make_uint2(pack_bf(hx, hy), pack_bf(hz, hw));
    uint2 L = make_uint2(pack_bf(ax - hx, ay - hy), pack_bf(az - hz, aw - hw));
    *(uint2*)(oh + (long long)w * 128 + lane * 4) = H;
    *(uint2*)(ol + (long long)w * 128 + lane * 4) = L;
}

// ---------------- fused CSR-fill + layer-0 aggregation (persistent, grid barrier) ----------------
__global__ void __launch_bounds__(FA_THREADS, 1)
k_fillagg(const void* __restrict__ edge, const float* __restrict__ xin,
          __nv_bfloat16* __restrict__ oh, __nv_bfloat16* __restrict__ ol,
          const float* __restrict__ eps_arr) {
    int tid = threadIdx.x;
    int gid = blockIdx.x * FA_THREADS + tid;
    int is64 = g_is64;
    for (int e = gid; e < N_EDGES; e += FA_BLOCKS * FA_THREADS) {
        int src = (int)load_idx(edge, e, is64);
        int dst = (int)load_idx(edge, (long long)N_EDGES + e, is64);
        int pos = atomicAdd(&g_cursor[dst], 1);
        g_srcs[pos] = src;
    }
    __syncthreads();
    if (tid == 0) {
        __threadfence();
        atomicAdd((int*)&g_gbar, 1);
        while (g_gbar < FA_BLOCKS) { }
    }
    __syncthreads();
    __threadfence();
    float eps = 1.0f + eps_arr[0];
    const float4* x4 = (const float4*)xin;
    int gw = gid >> 5, lane = tid & 31;
    const int NW = (FA_BLOCKS * FA_THREADS) / 32;
    for (int w = gw; w < N_NODES; w += NW)
        agg_node_f32<4>(x4, w, lane, eps, oh, ol);
}

// ---------------- aggregation from fp16 input (layers 1-3) ----------------
// lane covers cols lane*4..+3 -> one uint2 (4 halfs, 8 B) per row per lane.
__global__ void k_agg(const __half* __restrict__ xin,
                      __nv_bfloat16* __restrict__ oh, __nv_bfloat16* __restrict__ ol,
                      const float* __restrict__ eps_arr, int layer) {
    int w = (blockIdx.x * blockDim.x + threadIdx.x) >> 5;
    int lane = threadIdx.x & 31;
    if (w >= N_NODES) return;
    float eps = 1.0f + eps_arr[layer];
    const uint2* x2 = (const uint2*)xin;

    uint2 a = x2[(long long)w * 32 + lane];
    float2 a0 = __half22float2(*(__half2*)&a.x);
    float2 a1 = __half22float2(*(__half2*)&a.y);
    float ax = a0.x * eps, ay = a0.y * eps, az = a1.x * eps, aw = a1.y * eps;

    int e = g_rowoff[w], end = g_rowoff[w + 1];
    const int U = 8;
    for (; e + U - 1 < end; e += U) {
        int ss[U];
        uint2 vv[U];
        #pragma unroll
        for (int j = 0; j < U; j++) ss[j] = g_srcs[e + j];
        #pragma unroll
        for (int j = 0; j < U; j++) vv[j] = x2[(long long)ss[j] * 32 + lane];
        #pragma unroll
        for (int j = 0; j < U; j++) {
            float2 f0 = __half22float2(*(__half2*)&vv[j].x);
            float2 f1 = __half22float2(*(__half2*)&vv[j].y);
            ax += f0.x; ay += f0.y; az += f1.x; aw += f1.y;
        }
    }
    for (; e < end; e++) {
        uint2 v = x2[(long long)g_srcs[e] * 32 + lane];
        float2 f0 = __half22float2(*(__half2*)&v.x);
        float2 f1 = __half22float2(*(__half2*)&v.y);
        ax += f0.x; ay += f0.y; az += f1.x; aw += f1.y;
    }
    float hx = __bfloat162float(__float2bfloat16(ax));
    float hy = __bfloat162float(__float2bfloat16(ay));
    float hz = __bfloat162float(__float2bfloat16(az));
    float hw = __bfloat162float(__float2bfloat16(aw));
    uint2 H = make_uint2(pack_bf(hx, hy), pack_bf(hz, hw));
    uint2 L = make_uint2(pack_bf(ax - hx, ay - hy), pack_bf(az - hz, aw - hw));
    *(uint2*)(oh + (long long)w * 128 + lane * 4) = H;
    *(uint2*)(ol + (long long)w * 128 + lane * 4) = L;
}

// ---------------- fused per-layer GEMM pair (persistent HMMA) ----------------
// Warp tile m64n32 (wr=wid&1, wc=wid>>1): per K-step 12 ldsm4 + 48 MMA
// (was 24+48) — third less issue pressure. Combo-major MMA order.
// Per tile: T1 = relu(A@W1t^T + b1) -> hi/lo back into A smem buffer ->
// OUT = BN(relu(T1@W2t^T + b2)) -> fp16.

#define ASTR_B 272                      // padded row stride in bytes (136 bf16)
#define MAT_B (128 * ASTR_B)            // 34816 B per 128x128 matrix
#define SM_W1H 0
#define SM_W1L MAT_B
#define SM_W2H (2 * MAT_B)
#define SM_W2L (3 * MAT_B)
#define SM_AH  (4 * MAT_B)
#define SM_AL  (5 * MAT_B)
#define SM_TOTAL (6 * MAT_B)            // 208896 B -> 1 CTA/SM

__device__ __forceinline__ void ldsm4(unsigned* r, unsigned addr) {
    asm volatile("ldmatrix.sync.aligned.m8n8.x4.shared.b16 {%0,%1,%2,%3}, [%4];"
                 : "=r"(r[0]), "=r"(r[1]), "=r"(r[2]), "=r"(r[3]) : "r"(addr));
}
__device__ __forceinline__ void mma_bf16(float* d, const unsigned* a, const unsigned* b) {
    asm volatile("mma.sync.aligned.m16n8k16.row.col.f32.bf16.bf16.f32 "
                 "{%0,%1,%2,%3}, {%4,%5,%6,%7}, {%8,%9}, {%0,%1,%2,%3};"
                 : "+f"(d[0]), "+f"(d[1]), "+f"(d[2]), "+f"(d[3])
                 : "r"(a[0]), "r"(a[1]), "r"(a[2]), "r"(a[3]), "r"(b[0]), "r"(b[1]));
}
__device__ __forceinline__ void cp16(unsigned saddr, const void* g, int nbytes) {
    asm volatile("cp.async.cg.shared.global [%0], [%1], 16, %2;"
                 :: "r"(saddr), "l"(g), "r"(nbytes) : "memory");
}

// issue cp.asyncs for one 128x128 bf16 A tile (hi+lo) into SM_AH/SM_AL
__device__ __forceinline__ void issue_A(const __nv_bfloat16* __restrict__ Ah,
                                        const __nv_bfloat16* __restrict__ Al,
                                        int row0, unsigned sb, int tid) {
    #pragma unroll
    for (int it = 0; it < 8; it++) {
        int i = tid + it * 256;                  // 0..2047 16B chunks
        int r = i >> 4, c16 = i & 15;
        bool ok = (row0 + r) < N_NODES;
        const char* gh = (const char*)(Ah + (long long)(row0 + r) * 128) + c16 * 16;
        const char* gl = (const char*)(Al + (long long)(row0 + r) * 128) + c16 * 16;
        unsigned d = sb + SM_AH + (unsigned)(r * ASTR_B + c16 * 16);
        cp16(d, ok ? gh : (const char*)Ah, ok ? 16 : 0);
        cp16(d + MAT_B, ok ? gl : (const char*)Al, ok ? 16 : 0);
    }
}

// one 128x128 GEMM mainloop: m64n32 warp tile, combo-major (AhWh, AhWl, AlWh)
__device__ __forceinline__ void gemm_tile(unsigned aH0, unsigned aL0,
                                          unsigned bH, unsigned bL,
                                          float acc[4][4][4]) {
    #pragma unroll
    for (int ks = 0; ks < 8; ks++) {
        unsigned kb = (unsigned)(ks * 32);
        unsigned ah[4][4], al[4][4], bhr[2][4], blr[2][4];
        #pragma unroll
        for (int mt = 0; mt < 4; mt++) {
            ldsm4(ah[mt], aH0 + (unsigned)(mt * 16 * ASTR_B) + kb);
            ldsm4(al[mt], aL0 + (unsigned)(mt * 16 * ASTR_B) + kb);
        }
        #pragma unroll
        for (int np = 0; np < 2; np++) {
            ldsm4(bhr[np], bH + (unsigned)(np * 16 * ASTR_B) + kb);
            ldsm4(blr[np], bL + (unsigned)(np * 16 * ASTR_B) + kb);
        }
        #pragma unroll
        for (int mt = 0; mt < 4; mt++)
            #pragma unroll
            for (int nt = 0; nt < 4; nt++)
                mma_bf16(acc[mt][nt], ah[mt], &bhr[nt >> 1][(nt & 1) * 2]);
        #pragma unroll
        for (int mt = 0; mt < 4; mt++)
            #pragma unroll
            for (int nt = 0; nt < 4; nt++)
                mma_bf16(acc[mt][nt], ah[mt], &blr[nt >> 1][(nt & 1) * 2]);
        #pragma unroll
        for (int mt = 0; mt < 4; mt++)
            #pragma unroll
            for (int nt = 0; nt < 4; nt++)
                mma_bf16(acc[mt][nt], al[mt], &bhr[nt >> 1][(nt & 1) * 2]);
    }
}

__global__ void __launch_bounds__(256, 1)
k_layer(const __nv_bfloat16* __restrict__ Ah, const __nv_bfloat16* __restrict__ Al,
        const __nv_bfloat16* __restrict__ W1h, const __nv_bfloat16* __restrict__ W1l,
        const __nv_bfloat16* __restrict__ W2h, const __nv_bfloat16* __restrict__ W2l,
        const float* __restrict__ b1, const float* __restrict__ b2,
        __half* __restrict__ out16,
        const float* __restrict__ gamma, const float* __restrict__ beta,
        const float* __restrict__ mean,  const float* __restrict__ var) {
    extern __shared__ char smem[];
    unsigned sb;
    asm("{ .reg .u64 t; cvta.to.shared.u64 t, %1; cvt.u32.u64 %0, t; }" : "=r"(sb) : "l"(smem));
    int tid = threadIdx.x, wid = tid >> 5, lane = tid & 31;

    // stage 4 W matrices once + first A tile (single commit group)
    #pragma unroll
    for (int it = 0; it < 32; it++) {
        int i = tid + it * 256;                  // 0..8191 16B chunks
        int m = i >> 11;                         // matrix 0..3
        int j = i & 2047;
        int r = j >> 4, c16 = j & 15;
        const __nv_bfloat16* src = (m == 0) ? W1h : (m == 1) ? W1l : (m == 2) ? W2h : W2l;
        cp16(sb + (unsigned)(m * MAT_B + r * ASTR_B + c16 * 16),
             (const char*)(src + (long long)r * 128) + c16 * 16, 16);
    }
    int tile = blockIdx.x;
    if (tile < MTILES) issue_A(Ah, Al, tile * 128, sb, tid);
    asm volatile("cp.async.commit_group;" ::: "memory");

    int wr = wid & 1, wc = wid >> 1;      // warp tile: rows wr*64..+64, cols wc*32..+32
    int quad = lane >> 2, qi = lane & 3;

    // ldmatrix lane address components
    unsigned aoff = (unsigned)((wr * 64 + (lane & 15)) * ASTR_B + (lane >> 4) * 16);
    int bm = lane >> 3;
    int b_nt_off = bm >> 1;
    int b_kh = bm & 1;
    unsigned boff = (unsigned)((wc * 32 + b_nt_off * 8 + (lane & 7)) * ASTR_B + b_kh * 16);
    unsigned b1H = sb + SM_W1H + boff, b1L = sb + SM_W1L + boff;
    unsigned b2H = sb + SM_W2H + boff, b2L = sb + SM_W2L + boff;
    unsigned aH0 = sb + SM_AH + aoff, aL0 = sb + SM_AL + aoff;

    for (; tile < MTILES; tile += PERSIST_GRID) {
        asm volatile("cp.async.wait_group 0;" ::: "memory");
        __syncthreads();

        // ---- GEMM1: acc = A @ W1t^T ----
        float acc[4][4][4];
        #pragma unroll
        for (int mt = 0; mt < 4; mt++)
            #pragma unroll
            for (int nt = 0; nt < 4; nt++)
                #pragma unroll
                for (int j = 0; j < 4; j++) acc[mt][nt][j] = 0.f;
        gemm_tile(aH0, aL0, b1H, b1L, acc);
        __syncthreads();   // all warps done reading A before overwrite

        // ---- T1 = relu(acc + b1), hi/lo split, store into A buffer ----
        #pragma unroll
        for (int mt = 0; mt < 4; mt++) {
            int rr = wr * 64 + mt * 16 + quad;
            #pragma unroll
            for (int half = 0; half < 2; half++) {
                int r = rr + half * 8;
                #pragma unroll
                for (int nt = 0; nt < 4; nt++) {
                    int c = wc * 32 + nt * 8 + qi * 2;
                    float v0 = fmaxf(acc[mt][nt][half * 2] + __ldg(b1 + c), 0.f);
                    float v1 = fmaxf(acc[mt][nt][half * 2 + 1] + __ldg(b1 + c + 1), 0.f);
                    float h0 = __bfloat162float(__float2bfloat16(v0));
                    float h1 = __bfloat162float(__float2bfloat16(v1));
                    unsigned soff = (unsigned)(r * ASTR_B + c * 2);
                    *(unsigned*)(smem + SM_AH + soff) = pack_bf(h0, h1);
                    *(unsigned*)(smem + SM_AL + soff) = pack_bf(v0 - h0, v1 - h1);
                }
            }
        }
        __syncthreads();

        // ---- GEMM2: acc = T1 @ W2t^T ----
        #pragma unroll
        for (int mt = 0; mt < 4; mt++)
            #pragma unroll
            for (int nt = 0; nt < 4; nt++)
                #pragma unroll
                for (int j = 0; j < 4; j++) acc[mt][nt][j] = 0.f;
        gemm_tile(aH0, aL0, b2H, b2L, acc);
        __syncthreads();   // done reading T1; buffer free for next prefetch

        int next = tile + PERSIST_GRID;
        if (next < MTILES) issue_A(Ah, Al, next * 128, sb, tid);
        asm volatile("cp.async.commit_group;" ::: "memory");

        // ---- epilogue: BN(relu(acc + b2)) -> fp16 out ----
        int row0 = tile * 128;
        #pragma unroll
        for (int mt = 0; mt < 4; mt++) {
            int r0 = row0 + wr * 64 + mt * 16 + quad;
            #pragma unroll
            for (int half = 0; half < 2; half++) {
                int r = r0 + half * 8;
                if (r >= N_NODES) continue;
                #pragma unroll
                for (int nt = 0; nt < 4; nt++) {
                    int c = wc * 32 + nt * 8 + qi * 2;
                    float v0 = fmaxf(acc[mt][nt][half * 2] + __ldg(b2 + c), 0.f);
                    float v1 = fmaxf(acc[mt][nt][half * 2 + 1] + __ldg(b2 + c + 1), 0.f);
                    float s0 = __ldg(gamma + c) * rsqrtf(__ldg(var + c) + 1e-5f);
                    float s1 = __ldg(gamma + c + 1) * rsqrtf(__ldg(var + c + 1) + 1e-5f);
                    v0 = (v0 - __ldg(mean + c)) * s0 + __ldg(beta + c);
                    v1 = (v1 - __ldg(mean + c + 1)) * s1 + __ldg(beta + c + 1);
                    __half2 h2 = __floats2half2_rn(v0, v1);
                    *(__half2*)(out16 + (long long)r * 128 + c) = h2;
                }
            }
        }
    }
}

// ---------------- mean pool per graph (batch sorted, fp16 input) + scratch reset ----------------
__device__ __forceinline__ int lower_bound_batch(const void* batch, long long key, int is64) {
    int lo = 0, hi = N_NODES;
    while (lo < hi) {
        int mid = (lo + hi) >> 1;
        long long v = load_idx(batch, mid, is64);
        if (v < key) lo = mid + 1; else hi = mid;
    }
    return lo;
}

__global__ void k_pool(const __half* __restrict__ x, const void* __restrict__ batch) {
    int g = blockIdx.x;
    int f = threadIdx.x;
    __shared__ int s_beg, s_end;
    if (f == 0) {
        int is64 = g_is64;
        s_beg = lower_bound_batch(batch, g, is64);
        s_end = lower_bound_batch(batch, g + 1, is64);
    }
    __syncthreads();
    int beg = s_beg, end = s_end;
    float s = 0.f;
    for (int r = beg; r < end; r++) s += __half2float(x[(long long)r * HID + f]);
    float cnt = (float)(end - beg);
    g_pooled[g * HID + f] = s / fmaxf(cnt, 1.0f);

    // tail: reset CSR scratch + barriers for the next graph replay
    int gt = g * HID + f;
    for (int i = gt; i < N_NODES + 1; i += N_GRAPHS * HID) g_rowoff[i] = 0;
    if (gt < SCAN_B) g_bflag[gt] = 0;
    if (gt == 0) g_gbar = 0;
}

// ---------------- head: relu(pooled@W1+b1) @ W2 + b2, log_softmax ----------------
__global__ void k_head(const float* __restrict__ W1, const float* __restrict__ b1,
                       const float* __restrict__ W2, const float* __restrict__ b2,
                       float* __restrict__ out) {
    int g = blockIdx.x;
    int t = threadIdx.x;
    __shared__ float sp[HID], sh[HID], sl[OUT_DIM];
    __shared__ float smax, slse;
    sp[t] = g_pooled[g * HID + t];
    __syncthreads();
    float acc = b1[t];
    #pragma unroll 8
    for (int k = 0; k < HID; k++) acc += sp[k] * W1[k * HID + t];
    sh[t] = fmaxf(acc, 0.f);
    __syncthreads();
    if (t < OUT_DIM) {
        float a = b2[t];
        #pragma unroll 8
        for (int k = 0; k < HID; k++) a += sh[k] * W2[k * OUT_DIM + t];
        sl[t] = a;
    }
    __syncthreads();
    if (t == 0) {
        float m = -1e30f;
        for (int o = 0; o < OUT_DIM; o++) m = fmaxf(m, sl[o]);
        float s = 0.f;
        for (int o = 0; o < OUT_DIM; o++) s += expf(sl[o] - m);
        smax = m; slse = logf(s);
    }
    __syncthreads();
    if (t < OUT_DIM) out[g * OUT_DIM + t] = sl[t] - smax - slse;
}

// ---------------- launch ----------------
extern "C" void kernel_launch(void* const* d_in, const int* in_sizes, int n_in,
                              void* d_out, int out_size) {
    const float* x      = (const float*)d_in[0];
    const void*  edge   = d_in[1];
    const void*  batch  = d_in[2];
    const float* W1s    = (const float*)d_in[3];
    const float* b1s    = (const float*)d_in[4];
    const float* W2s    = (const float*)d_in[5];
    const float* b2s    = (const float*)d_in[6];
    const float* gammas = (const float*)d_in[7];
    const float* betas  = (const float*)d_in[8];
    const float* means  = (const float*)d_in[9];
    const float* vars   = (const float*)d_in[10];
    const float* epsarr = (const float*)d_in[11];
    const float* lin1W  = (const float*)d_in[12];
    const float* lin1b  = (const float*)d_in[13];
    const float* lin2W  = (const float*)d_in[14];
    const float* lin2b  = (const float*)d_in[15];
    float* out = (float*)d_out;

    __half *A16;
    __nv_bfloat16 *Bh, *Bl, *Wth, *Wtl;
    cudaGetSymbolAddress((void**)&A16, g_Ah16);
    cudaGetSymbolAddress((void**)&Bh, g_Bh);
    cudaGetSymbolAddress((void**)&Bl, g_Bl);
    cudaGetSymbolAddress((void**)&Wth, g_Wth);
    cudaGetSymbolAddress((void**)&Wtl, g_Wtl);

    cudaFuncSetAttribute(k_layer, cudaFuncAttributeMaxDynamicSharedMemorySize, SM_TOTAL);

    // CSR build + weight prep; fillagg fuses fill with layer-0 agg so that
    // k_layer is launch #4 (the ncu capture slot)
    k_count<<<EDGE_BLOCKS + WPREP_BLOCKS, 256>>>(edge, W1s, W2s);
    k_scanall<<<SCAN_B, 1024>>>();
    k_fillagg<<<FA_BLOCKS, FA_THREADS>>>(edge, x, Bh, Bl, epsarr);

    const int agg_blocks = (N_NODES * 32 + 255) / 256;

    for (int l = 0; l < N_LAYERS; l++) {
        if (l > 0)
            k_agg<<<agg_blocks, 256>>>(A16, Bh, Bl, epsarr, l);
        k_layer<<<PERSIST_GRID, 256, SM_TOTAL>>>(
            Bh, Bl,
            Wth + (l * 2) * 16384, Wtl + (l * 2) * 16384,
            Wth + (l * 2 + 1) * 16384, Wtl + (l * 2 + 1) * 16384,
            b1s + l * HID, b2s + l * HID,
            A16,
            gammas + l * HID, betas + l * HID, means + l * HID, vars + l * HID);
    }

    k_pool<<<N_GRAPHS, HID>>>(A16, batch);
    k_head<<<N_GRAPHS, HID>>>(lin1W, lin1b, lin2W, lin2b, out);
}

// round 16
// speedup vs baseline: 1.5937x; 1.1322x over previous
#include <cuda_runtime.h>
#include <cuda_fp16.h>
#include <stdint.h>
#include <math.h>

#define N_NODES 50000
#define N_EDGES 800000
#define HID     128
#define OUT_DIM 40
#define N_LAYERS 4
#define N_GRAPHS 128
#define SCAN_B  49           // ceil(50000/1024)
#define EDGE_BLOCKS 3125     // ceil(800000/256)
#define WPREP_ELEMS (8 * HID * HID)
#define WPREP_BLOCKS ((WPREP_ELEMS + 255) / 256)
#define MTILES ((N_NODES + 127) / 128)     // 391
#define PERSIST_GRID 148                   // one wave, 1 CTA/SM
#define FA_BLOCKS 148
#define FA_THREADS 1024

// ---------------- scratch (static device globals; zero-initialized at load) ----------------
__device__ __half g_X16[N_NODES * HID];                 // fp16 node features (layer output)
__device__ __half g_B16[N_NODES * HID];                 // fp16 agg output (layer GEMM input)
__device__ __half g_Wh16[WPREP_ELEMS];                  // transposed weights hi: [mat][n][k]
__device__ __half g_Wl16[WPREP_ELEMS];                  // transposed weights lo (fp16 subnormal range)
__device__ int   g_rowoff[N_NODES + 1];                 // zeroed at load + k_pool tail
__device__ int   g_cursor[N_NODES];
__device__ int   g_srcs[N_EDGES];
__device__ volatile int g_bsum[SCAN_B];
__device__ volatile int g_bflag[SCAN_B];                // zeroed at load + k_pool tail
__device__ volatile int g_gbar;                         // fillagg grid barrier; reset in k_pool
__device__ int   g_is64;
__device__ float g_pooled[N_GRAPHS * HID];

// ---------------- helpers ----------------
__device__ __forceinline__ long long load_idx(const void* p, long long i, int is64) {
    if (is64) return ((const long long*)p)[i];
    return (long long)((const int*)p)[i];
}

__device__ __forceinline__ unsigned pack_h2(float a, float b) {
    __half2 t = __floats2half2_rn(a, b);
    return *reinterpret_cast<unsigned*>(&t);
}

// ---------------- CSR count (by dst) + weight split/transpose (extra blocks) ----------------
__global__ void k_count(const void* __restrict__ edge,
                        const float* __restrict__ W1s, const float* __restrict__ W2s) {
    int b = blockIdx.x;
    if (b >= EDGE_BLOCKS) {
        // weight prep: Wt[mat][n][k] = W[mat][k][n] split into fp16 hi/lo
        int t = (b - EDGE_BLOCKS) * 256 + threadIdx.x;
        if (t < WPREP_ELEMS) {
            int mat = t >> 14, rem = t & 16383;
            int n = rem >> 7, k = rem & 127;
            int l = mat >> 1;
            float w = (mat & 1) ? W2s[l * 16384 + k * 128 + n]
                                : W1s[l * 16384 + k * 128 + n];
            __half h = __float2half_rn(w);
            g_Wh16[t] = h;
            g_Wl16[t] = __float2half_rn(w - __half2float(h));
        }
        return;
    }
    __shared__ int s_is64;
    int t = threadIdx.x;
    if (t == 0) s_is64 = 1;
    __syncthreads();
    if (t < 64) {
        // int32 data reinterpreted as int64 has a random node id in the high
        // word (invalid w.p. ~1), so 64 valid samples => genuine int64.
        long long v = ((const long long*)edge)[(long long)t * 12347 + 5];
        if (v < 0 || v >= N_NODES) atomicAnd(&s_is64, 0);
    }
    __syncthreads();
    int is64 = s_is64;
    if (b == 0 && t == 0) g_is64 = is64;
    int e = b * blockDim.x + t;
    if (e < N_EDGES) {
        int dst = (int)load_idx(edge, (long long)N_EDGES + e, is64);
        atomicAdd(&g_rowoff[dst], 1);
    }
}

// ---------------- single-kernel scan: block scan + decoupled lookback ----------------
__global__ void k_scanall() {
    __shared__ int part[1024];
    __shared__ int s_pref;
    int t = threadIdx.x, bid = blockIdx.x;
    int idx = bid * 1024 + t;
    int c = (idx < N_NODES) ? g_rowoff[idx] : 0;
    part[t] = c;
    __syncthreads();
    #pragma unroll
    for (int off = 1; off < 1024; off <<= 1) {
        int v = (t >= off) ? part[t - off] : 0;
        __syncthreads();
        part[t] += v;
        __syncthreads();
    }
    if (t == 1023) {
        g_bsum[bid] = part[1023];
        __threadfence();
        g_bflag[bid] = 1;
    }
    if (t < 32) {
        int s = 0;
        for (int p = t; p < bid; p += 32) {
            while (g_bflag[p] == 0) { }
            s += g_bsum[p];
        }
        #pragma unroll
        for (int o = 16; o; o >>= 1) s += __shfl_xor_sync(0xffffffffu, s, o);
        if (t == 0) s_pref = s;
    }
    __syncthreads();
    int pref = s_pref;
    if (idx < N_NODES) {
        int v = pref + part[t] - c;
        g_rowoff[idx] = v;
        g_cursor[idx] = v;
    }
    if (bid == SCAN_B - 1 && t == 1023) g_rowoff[N_NODES] = N_EDGES;
}

// ---------------- aggregation from fp32 input (layer 0), fp16 output ----------------
template <int U>
__device__ __forceinline__ void agg_node_f32(const float4* __restrict__ x4, int w, int lane,
                                             float eps, __half* __restrict__ o16) {
    float4 a = x4[(long long)w * 32 + lane];
    float ax = a.x * eps, ay = a.y * eps, az = a.z * eps, aw = a.w * eps;
    int e = g_rowoff[w], end = g_rowoff[w + 1];
    for (; e + U - 1 < end; e += U) {
        int ss[U];
        float4 vv[U];
        #pragma unroll
        for (int j = 0; j < U; j++) ss[j] = g_srcs[e + j];
        #pragma unroll
        for (int j = 0; j < U; j++) vv[j] = x4[(long long)ss[j] * 32 + lane];
        #pragma unroll
        for (int j = 0; j < U; j++) {
            ax += vv[j].x; ay += vv[j].y; az += vv[j].z; aw += vv[j].w;
        }
    }
    for (; e < end; e++) {
        int s = g_srcs[e];
        float4 v = x4[(long long)s * 32 + lane];
        ax += v.x; ay += v.y; az += v.z; aw += v.w;
    }
    uint2 O = make_uint2(pack_h2(ax, ay), pack_h2(az, aw));
    *(uint2*)(o16 + (long long)w * 128 + lane * 4) = O;
}

// ---------------- fused CSR-fill + layer-0 aggregation (persistent, grid barrier) ----------------
__global__ void __launch_bounds__(FA_THREADS, 1)
k_fillagg(const void* __restrict__ edge, const float* __restrict__ xin,
          __half* __restrict__ o16, const float* __restrict__ eps_arr) {
    int tid = threadIdx.x;
    int gid = blockIdx.x * FA_THREADS + tid;
    int is64 = g_is64;
    for (int e = gid; e < N_EDGES; e += FA_BLOCKS * FA_THREADS) {
        int src = (int)load_idx(edge, e, is64);
        int dst = (int)load_idx(edge, (long long)N_EDGES + e, is64);
        int pos = atomicAdd(&g_cursor[dst], 1);
        g_srcs[pos] = src;
    }
    __syncthreads();
    if (tid == 0) {
        __threadfence();
        atomicAdd((int*)&g_gbar, 1);
        while (g_gbar < FA_BLOCKS) { }
    }
    __syncthreads();
    __threadfence();
    float eps = 1.0f + eps_arr[0];
    const float4* x4 = (const float4*)xin;
    int gw = gid >> 5, lane = tid & 31;
    const int NW = (FA_BLOCKS * FA_THREADS) / 32;
    for (int w = gw; w < N_NODES; w += NW)
        agg_node_f32<4>(x4, w, lane, eps, o16);
}

// ---------------- aggregation from fp16 input (layers 1-3), fp16 output ----------------
__global__ void k_agg(const __half* __restrict__ xin, __half* __restrict__ o16,
                      const float* __restrict__ eps_arr, int layer) {
    int w = (blockIdx.x * blockDim.x + threadIdx.x) >> 5;
    int lane = threadIdx.x & 31;
    if (w >= N_NODES) return;
    float eps = 1.0f + eps_arr[layer];
    const uint2* x2 = (const uint2*)xin;

    uint2 a = x2[(long long)w * 32 + lane];
    float2 a0 = __half22float2(*(__half2*)&a.x);
    float2 a1 = __half22float2(*(__half2*)&a.y);
    float ax = a0.x * eps, ay = a0.y * eps, az = a1.x * eps, aw = a1.y * eps;

    int e = g_rowoff[w], end = g_rowoff[w + 1];
    const int U = 8;
    for (; e + U - 1 < end; e += U) {
        int ss[U];
        uint2 vv[U];
        #pragma unroll
        for (int j = 0; j < U; j++) ss[j] = g_srcs[e + j];
        #pragma unroll
        for (int j = 0; j < U; j++) vv[j] = x2[(long long)ss[j] * 32 + lane];
        #pragma unroll
        for (int j = 0; j < U; j++) {
            float2 f0 = __half22float2(*(__half2*)&vv[j].x);
            float2 f1 = __half22float2(*(__half2*)&vv[j].y);
            ax += f0.x; ay += f0.y; az += f1.x; aw += f1.y;
        }
    }
    for (; e < end; e++) {
        uint2 v = x2[(long long)g_srcs[e] * 32 + lane];
        float2 f0 = __half22float2(*(__half2*)&v.x);
        float2 f1 = __half22float2(*(__half2*)&v.y);
        ax += f0.x; ay += f0.y; az += f1.x; aw += f1.y;
    }
    uint2 O = make_uint2(pack_h2(ax, ay), pack_h2(az, aw));
    *(uint2*)(o16 + (long long)w * 128 + lane * 4) = O;
}

// ---------------- fused per-layer GEMM pair (persistent HMMA, fp16 operands) ----------------
// A single fp16 matrix (agg output / T1), W in fp16 hi/lo -> 2 combos per GEMM
// (A*Wh + A*Wl). Warp tile m64n32. A double-buffered via cp.async.
// Per tile: T1 = relu(A@W1t^T + b1) -> fp16 back into A buffer ->
// OUT = BN(relu(T1@W2t^T + b2)) -> fp16.

#define ASTR_B 272                      // padded row stride in bytes
#define MAT_B (128 * ASTR_B)            // 34816 B per 128-row matrix
#define SM_W1H 0
#define SM_W1L MAT_B
#define SM_W2H (2 * MAT_B)
#define SM_W2L (3 * MAT_B)
#define SM_AB(i) ((4 + (i)) * MAT_B)    // A fp16 double buffer
#define SM_TOTAL (6 * MAT_B)            // 208896 B -> 1 CTA/SM

__device__ __forceinline__ void ldsm4(unsigned* r, unsigned addr) {
    asm volatile("ldmatrix.sync.aligned.m8n8.x4.shared.b16 {%0,%1,%2,%3}, [%4];"
                 : "=r"(r[0]), "=r"(r[1]), "=r"(r[2]), "=r"(r[3]) : "r"(addr));
}
__device__ __forceinline__ void mma_f16(float* d, const unsigned* a, const unsigned* b) {
    asm volatile("mma.sync.aligned.m16n8k16.row.col.f32.f16.f16.f32 "
                 "{%0,%1,%2,%3}, {%4,%5,%6,%7}, {%8,%9}, {%0,%1,%2,%3};"
                 : "+f"(d[0]), "+f"(d[1]), "+f"(d[2]), "+f"(d[3])
                 : "r"(a[0]), "r"(a[1]), "r"(a[2]), "r"(a[3]), "r"(b[0]), "r"(b[1]));
}
__device__ __forceinline__ void cp16(unsigned saddr, const void* g, int nbytes) {
    asm volatile("cp.async.cg.shared.global [%0], [%1], 16, %2;"
                 :: "r"(saddr), "l"(g), "r"(nbytes) : "memory");
}

// issue cp.asyncs for one 128x128 fp16 A tile into buffer at sbuf
__device__ __forceinline__ void issue_A(const __half* __restrict__ A16,
                                        int row0, unsigned sbuf, int tid) {
    #pragma unroll
    for (int it = 0; it < 8; it++) {
        int i = tid + it * 256;                  // 0..2047 16B chunks (128 rows x 16)
        int r = i >> 4, c16 = i & 15;
        bool ok = (row0 + r) < N_NODES;
        const char* gp = (const char*)(A16 + (long long)(row0 + r) * 128) + c16 * 16;
        cp16(sbuf + (unsigned)(r * ASTR_B + c16 * 16), ok ? gp : (const char*)A16, ok ? 16 : 0);
    }
}

// one 128x128 GEMM mainloop: m64n32 warp tile, 2 combos (A*Wh, A*Wl)
__device__ __forceinline__ void gemm_tile(unsigned aBase, unsigned bH, unsigned bL,
                                          float acc[4][4][4]) {
    #pragma unroll
    for (int ks = 0; ks < 8; ks++) {
        unsigned kb = (unsigned)(ks * 32);
        unsigned av[4][4], bhr[2][4], blr[2][4];
        #pragma unroll
        for (int mt = 0; mt < 4; mt++)
            ldsm4(av[mt], aBase + (unsigned)(mt * 16 * ASTR_B) + kb);
        #pragma unroll
        for (int np = 0; np < 2; np++) {
            ldsm4(bhr[np], bH + (unsigned)(np * 16 * ASTR_B) + kb);
            ldsm4(blr[np], bL + (unsigned)(np * 16 * ASTR_B) + kb);
        }
        #pragma unroll
        for (int mt = 0; mt < 4; mt++)
            #pragma unroll
            for (int nt = 0; nt < 4; nt++)
                mma_f16(acc[mt][nt], av[mt], &bhr[nt >> 1][(nt & 1) * 2]);
        #pragma unroll
        for (int mt = 0; mt < 4; mt++)
            #pragma unroll
            for (int nt = 0; nt < 4; nt++)
                mma_f16(acc[mt][nt], av[mt], &blr[nt >> 1][(nt & 1) * 2]);
    }
}

__global__ void __launch_bounds__(256, 1)
k_layer(const __half* __restrict__ A16,
        const __half* __restrict__ W1h, const __half* __restrict__ W1l,
        const __half* __restrict__ W2h, const __half* __restrict__ W2l,
        const float* __restrict__ b1, const float* __restrict__ b2,
        __half* __restrict__ out16,
        const float* __restrict__ gamma, const float* __restrict__ beta,
        const float* __restrict__ mean,  const float* __restrict__ var) {
    extern __shared__ char smem[];
    unsigned sb;
    asm("{ .reg .u64 t; cvta.to.shared.u64 t, %1; cvt.u32.u64 %0, t; }" : "=r"(sb) : "l"(smem));
    int tid = threadIdx.x, wid = tid >> 5, lane = tid & 31;

    // stage 4 W matrices once + first A tile (group 0)
    #pragma unroll
    for (int it = 0; it < 32; it++) {
        int i = tid + it * 256;                  // 0..8191 16B chunks
        int m = i >> 11;                         // matrix 0..3
        int j = i & 2047;
        int r = j >> 4, c16 = j & 15;
        const __half* src = (m == 0) ? W1h : (m == 1) ? W1l : (m == 2) ? W2h : W2l;
        cp16(sb + (unsigned)(m * MAT_B + r * ASTR_B + c16 * 16),
             (const char*)(src + (long long)r * 128) + c16 * 16, 16);
    }
    int tile = blockIdx.x;
    if (tile < MTILES) issue_A(A16, tile * 128, sb + SM_AB(0), tid);
    asm volatile("cp.async.commit_group;" ::: "memory");

    int wr = wid & 1, wc = wid >> 1;      // warp tile: rows wr*64..+64, cols wc*32..+32
    int quad = lane >> 2, qi = lane & 3;

    // ldmatrix lane address components
    unsigned aoff = (unsigned)((wr * 64 + (lane & 15)) * ASTR_B + (lane >> 4) * 16);
    int bm = lane >> 3;
    int b_nt_off = bm >> 1;
    int b_kh = bm & 1;
    unsigned boff = (unsigned)((wc * 32 + b_nt_off * 8 + (lane & 7)) * ASTR_B + b_kh * 16);
    unsigned b1H = sb + SM_W1H + boff, b1L = sb + SM_W1L + boff;
    unsigned b2H = sb + SM_W2H + boff, b2L = sb + SM_W2L + boff;

    int bufi = 0;
    for (; tile < MTILES; tile += PERSIST_GRID, bufi ^= 1) {
        // prefetch next tile into the other buffer (overlaps both GEMMs)
        int next = tile + PERSIST_GRID;
        if (next < MTILES) issue_A(A16, next * 128, sb + SM_AB(bufi ^ 1), tid);
        asm volatile("cp.async.commit_group;" ::: "memory");
        asm volatile("cp.async.wait_group 1;" ::: "memory");   // current tile ready
        __syncthreads();

        unsigned aBase = sb + SM_AB(bufi) + aoff;

        // ---- GEMM1: acc = A @ W1t^T ----
        float acc[4][4][4];
        #pragma unroll
        for (int mt = 0; mt < 4; mt++)
            #pragma unroll
            for (int nt = 0; nt < 4; nt++)
                #pragma unroll
                for (int j = 0; j < 4; j++) acc[mt][nt][j] = 0.f;
        gemm_tile(aBase, b1H, b1L, acc);
        __syncthreads();   // all warps done reading A before overwrite

        // ---- T1 = relu(acc + b1) -> fp16 into current A buffer ----
        #pragma unroll
        for (int mt = 0; mt < 4; mt++) {
            int rr = wr * 64 + mt * 16 + quad;
            #pragma unroll
            for (int half = 0; half < 2; half++) {
                int r = rr + half * 8;
                #pragma unroll
                for (int nt = 0; nt < 4; nt++) {
                    int c = wc * 32 + nt * 8 + qi * 2;
                    float v0 = fmaxf(acc[mt][nt][half * 2] + __ldg(b1 + c), 0.f);
                    float v1 = fmaxf(acc[mt][nt][half * 2 + 1] + __ldg(b1 + c + 1), 0.f);
                    *(unsigned*)(smem + SM_AB(bufi) + r * ASTR_B + c * 2) = pack_h2(v0, v1);
                }
            }
        }
        __syncthreads();

        // ---- GEMM2: acc = T1 @ W2t^T ----
        #pragma unroll
        for (int mt = 0; mt < 4; mt++)
            #pragma unroll
            for (int nt = 0; nt < 4; nt++)
                #pragma unroll
                for (int j = 0; j < 4; j++) acc[mt][nt][j] = 0.f;
        gemm_tile(aBase, b2H, b2L, acc);
        __syncthreads();   // done reading T1; buffer free for next iter's prefetch

        // ---- epilogue: BN(relu(acc + b2)) -> fp16 out ----
        int row0 = tile * 128;
        #pragma unroll
        for (int mt = 0; mt < 4; mt++) {
            int r0 = row0 + wr * 64 + mt * 16 + quad;
            #pragma unroll
            for (int half = 0; half < 2; half++) {
                int r = r0 + half * 8;
                if (r >= N_NODES) continue;
                #pragma unroll
                for (int nt = 0; nt < 4; nt++) {
                    int c = wc * 32 + nt * 8 + qi * 2;
                    float v0 = fmaxf(acc[mt][nt][half * 2] + __ldg(b2 + c), 0.f);
                    float v1 = fmaxf(acc[mt][nt][half * 2 + 1] + __ldg(b2 + c + 1), 0.f);
                    float s0 = __ldg(gamma + c) * rsqrtf(__ldg(var + c) + 1e-5f);
                    float s1 = __ldg(gamma + c + 1) * rsqrtf(__ldg(var + c + 1) + 1e-5f);
                    v0 = (v0 - __ldg(mean + c)) * s0 + __ldg(beta + c);
                    v1 = (v1 - __ldg(mean + c + 1)) * s1 + __ldg(beta + c + 1);
                    *(unsigned*)(out16 + (long long)r * 128 + c) = pack_h2(v0, v1);
                }
            }
        }
    }
}

// ---------------- mean pool per graph (batch sorted, fp16 input) + scratch reset ----------------
__device__ __forceinline__ int lower_bound_batch(const void* batch, long long key, int is64) {
    int lo = 0, hi = N_NODES;
    while (lo < hi) {
        int mid = (lo + hi) >> 1;
        long long v = load_idx(batch, mid, is64);
        if (v < key) lo = mid + 1; else hi = mid;
    }
    return lo;
}

__global__ void k_pool(const __half* __restrict__ x, const void* __restrict__ batch) {
    int g = blockIdx.x;
    int f = threadIdx.x;
    __shared__ int s_beg, s_end;
    if (f == 0) {
        int is64 = g_is64;
        s_beg = lower_bound_batch(batch, g, is64);
        s_end = lower_bound_batch(batch, g + 1, is64);
    }
    __syncthreads();
    int beg = s_beg, end = s_end;
    float s = 0.f;
    for (int r = beg; r < end; r++) s += __half2float(x[(long long)r * HID + f]);
    float cnt = (float)(end - beg);
    g_pooled[g * HID + f] = s / fmaxf(cnt, 1.0f);

    // tail: reset CSR scratch + barriers for the next graph replay
    int gt = g * HID + f;
    for (int i = gt; i < N_NODES + 1; i += N_GRAPHS * HID) g_rowoff[i] = 0;
    if (gt < SCAN_B) g_bflag[gt] = 0;
    if (gt == 0) g_gbar = 0;
}

// ---------------- head: relu(pooled@W1+b1) @ W2 + b2, log_softmax ----------------
__global__ void k_head(const float* __restrict__ W1, const float* __restrict__ b1,
                       const float* __restrict__ W2, const float* __restrict__ b2,
                       float* __restrict__ out) {
    int g = blockIdx.x;
    int t = threadIdx.x;
    __shared__ float sp[HID], sh[HID], sl[OUT_DIM];
    __shared__ float smax, slse;
    sp[t] = g_pooled[g * HID + t];
    __syncthreads();
    float acc = b1[t];
    #pragma unroll 8
    for (int k = 0; k < HID; k++) acc += sp[k] * W1[k * HID + t];
    sh[t] = fmaxf(acc, 0.f);
    __syncthreads();
    if (t < OUT_DIM) {
        float a = b2[t];
        #pragma unroll 8
        for (int k = 0; k < HID; k++) a += sh[k] * W2[k * OUT_DIM + t];
        sl[t] = a;
    }
    __syncthreads();
    if (t == 0) {
        float m = -1e30f;
        for (int o = 0; o < OUT_DIM; o++) m = fmaxf(m, sl[o]);
        float s = 0.f;
        for (int o = 0; o < OUT_DIM; o++) s += expf(sl[o] - m);
        smax = m; slse = logf(s);
    }
    __syncthreads();
    if (t < OUT_DIM) out[g * OUT_DIM + t] = sl[t] - smax - slse;
}

// ---------------- launch ----------------
extern "C" void kernel_launch(void* const* d_in, const int* in_sizes, int n_in,
                              void* d_out, int out_size) {
    const float* x      = (const float*)d_in[0];
    const void*  edge   = d_in[1];
    const void*  batch  = d_in[2];
    const float* W1s    = (const float*)d_in[3];
    const float* b1s    = (const float*)d_in[4];
    const float* W2s    = (const float*)d_in[5];
    const float* b2s    = (const float*)d_in[6];
    const float* gammas = (const float*)d_in[7];
    const float* betas  = (const float*)d_in[8];
    const float* means  = (const float*)d_in[9];
    const float* vars   = (const float*)d_in[10];
    const float* epsarr = (const float*)d_in[11];
    const float* lin1W  = (const float*)d_in[12];
    const float* lin1b  = (const float*)d_in[13];
    const float* lin2W  = (const float*)d_in[14];
    const float* lin2b  = (const float*)d_in[15];
    float* out = (float*)d_out;

    __half *X16, *B16, *Wh16, *Wl16;
    cudaGetSymbolAddress((void**)&X16, g_X16);
    cudaGetSymbolAddress((void**)&B16, g_B16);
    cudaGetSymbolAddress((void**)&Wh16, g_Wh16);
    cudaGetSymbolAddress((void**)&Wl16, g_Wl16);

    cudaFuncSetAttribute(k_layer, cudaFuncAttributeMaxDynamicSharedMemorySize, SM_TOTAL);

    // CSR build + weight prep; fillagg fuses fill with layer-0 agg so that
    // k_layer is launch #4 (the ncu capture slot)
    k_count<<<EDGE_BLOCKS + WPREP_BLOCKS, 256>>>(edge, W1s, W2s);
    k_scanall<<<SCAN_B, 1024>>>();
    k_fillagg<<<FA_BLOCKS, FA_THREADS>>>(edge, x, B16, epsarr);

    const int agg_blocks = (N_NODES * 32 + 255) / 256;

    for (int l = 0; l < N_LAYERS; l++) {
        if (l > 0)
            k_agg<<<agg_blocks, 256>>>(X16, B16, epsarr, l);
        k_layer<<<PERSIST_GRID, 256, SM_TOTAL>>>(
            B16,
            Wh16 + (l * 2) * 16384, Wl16 + (l * 2) * 16384,
            Wh16 + (l * 2 + 1) * 16384, Wl16 + (l * 2 + 1) * 16384,
            b1s + l * HID, b2s + l * HID,
            X16,
            gammas + l * HID, betas + l * HID, means + l * HID, vars + l * HID);
    }

    k_pool<<<N_GRAPHS, HID>>>(X16, batch);
    k_head<<<N_GRAPHS, HID>>>(lin1W, lin1b, lin2W, lin2b, out);
}

// round 17
// speedup vs baseline: 1.5960x; 1.0014x over previous
#include <cuda_runtime.h>
#include <cuda_fp16.h>
#include <stdint.h>
#include <math.h>

#define N_NODES 50000
#define N_EDGES 800000
#define HID     128
#define OUT_DIM 40
#define N_LAYERS 4
#define N_GRAPHS 128
#define SCAN_B  49           // ceil(50000/1024)
#define EDGE_BLOCKS 3125     // ceil(800000/256)
#define WPREP_ELEMS (8 * HID * HID)
#define WPREP_BLOCKS ((WPREP_ELEMS + 255) / 256)
#define MTILES ((N_NODES + 127) / 128)     // 391
#define PERSIST_GRID 148                   // one wave, 1 CTA/SM
#define FA_BLOCKS 148
#define FA_THREADS 1024

// ---------------- scratch (static device globals; zero-initialized at load) ----------------
__device__ __half g_X16[N_NODES * HID];                 // fp16 node features (layer output)
__device__ __half g_B16[N_NODES * HID];                 // fp16 agg output (layer GEMM input)
__device__ __half g_Wh16[WPREP_ELEMS];                  // transposed weights hi: [mat][n][k]
__device__ __half g_Wl16[WPREP_ELEMS];                  // transposed weights lo (fp16 subnormal range)
__device__ int   g_rowoff[N_NODES + 1];                 // zeroed at load + k_pool tail
__device__ int   g_cursor[N_NODES];
__device__ int   g_srcs[N_EDGES];
__device__ volatile int g_bsum[SCAN_B];
__device__ volatile int g_bflag[SCAN_B];                // zeroed at load + k_pool tail
__device__ volatile int g_gbar;                         // fillagg grid barrier; reset in k_pool
__device__ int   g_is64;
__device__ float g_pooled[N_GRAPHS * HID];

// ---------------- helpers ----------------
__device__ __forceinline__ long long load_idx(const void* p, long long i, int is64) {
    if (is64) return ((const long long*)p)[i];
    return (long long)((const int*)p)[i];
}

__device__ __forceinline__ unsigned pack_h2(float a, float b) {
    __half2 t = __floats2half2_rn(a, b);
    return *reinterpret_cast<unsigned*>(&t);
}

// ---------------- CSR count (by dst) + weight split/transpose (extra blocks) ----------------
__global__ void k_count(const void* __restrict__ edge,
                        const float* __restrict__ W1s, const float* __restrict__ W2s) {
    int b = blockIdx.x;
    if (b >= EDGE_BLOCKS) {
        // weight prep: Wt[mat][n][k] = W[mat][k][n] split into fp16 hi/lo
        int t = (b - EDGE_BLOCKS) * 256 + threadIdx.x;
        if (t < WPREP_ELEMS) {
            int mat = t >> 14, rem = t & 16383;
            int n = rem >> 7, k = rem & 127;
            int l = mat >> 1;
            float w = (mat & 1) ? W2s[l * 16384 + k * 128 + n]
                                : W1s[l * 16384 + k * 128 + n];
            __half h = __float2half_rn(w);
            g_Wh16[t] = h;
            g_Wl16[t] = __float2half_rn(w - __half2float(h));
        }
        return;
    }
    __shared__ int s_is64;
    int t = threadIdx.x;
    if (t == 0) s_is64 = 1;
    __syncthreads();
    if (t < 64) {
        // int32 data reinterpreted as int64 has a random node id in the high
        // word (invalid w.p. ~1), so 64 valid samples => genuine int64.
        long long v = ((const long long*)edge)[(long long)t * 12347 + 5];
        if (v < 0 || v >= N_NODES) atomicAnd(&s_is64, 0);
    }
    __syncthreads();
    int is64 = s_is64;
    if (b == 0 && t == 0) g_is64 = is64;
    int e = b * blockDim.x + t;
    if (e < N_EDGES) {
        int dst = (int)load_idx(edge, (long long)N_EDGES + e, is64);
        atomicAdd(&g_rowoff[dst], 1);
    }
}

// ---------------- single-kernel scan: block scan + decoupled lookback ----------------
__global__ void k_scanall() {
    __shared__ int part[1024];
    __shared__ int s_pref;
    int t = threadIdx.x, bid = blockIdx.x;
    int idx = bid * 1024 + t;
    int c = (idx < N_NODES) ? g_rowoff[idx] : 0;
    part[t] = c;
    __syncthreads();
    #pragma unroll
    for (int off = 1; off < 1024; off <<= 1) {
        int v = (t >= off) ? part[t - off] : 0;
        __syncthreads();
        part[t] += v;
        __syncthreads();
    }
    if (t == 1023) {
        g_bsum[bid] = part[1023];
        __threadfence();
        g_bflag[bid] = 1;
    }
    if (t < 32) {
        int s = 0;
        for (int p = t; p < bid; p += 32) {
            while (g_bflag[p] == 0) { }
            s += g_bsum[p];
        }
        #pragma unroll
        for (int o = 16; o; o >>= 1) s += __shfl_xor_sync(0xffffffffu, s, o);
        if (t == 0) s_pref = s;
    }
    __syncthreads();
    int pref = s_pref;
    if (idx < N_NODES) {
        int v = pref + part[t] - c;
        g_rowoff[idx] = v;
        g_cursor[idx] = v;
    }
    if (bid == SCAN_B - 1 && t == 1023) g_rowoff[N_NODES] = N_EDGES;
}

// ---------------- aggregation from fp32 input (layer 0), fp16 output ----------------
template <int U>
__device__ __forceinline__ void agg_node_f32(const float4* __restrict__ x4, int w, int lane,
                                             float eps, __half* __restrict__ o16) {
    float4 a = x4[(long long)w * 32 + lane];
    float ax = a.x * eps, ay = a.y * eps, az = a.z * eps, aw = a.w * eps;
    int e = g_rowoff[w], end = g_rowoff[w + 1];
    for (; e + U - 1 < end; e += U) {
        int ss[U];
        float4 vv[U];
        #pragma unroll
        for (int j = 0; j < U; j++) ss[j] = g_srcs[e + j];
        #pragma unroll
        for (int j = 0; j < U; j++) vv[j] = x4[(long long)ss[j] * 32 + lane];
        #pragma unroll
        for (int j = 0; j < U; j++) {
            ax += vv[j].x; ay += vv[j].y; az += vv[j].z; aw += vv[j].w;
        }
    }
    for (; e < end; e++) {
        int s = g_srcs[e];
        float4 v = x4[(long long)s * 32 + lane];
        ax += v.x; ay += v.y; az += v.z; aw += v.w;
    }
    uint2 O = make_uint2(pack_h2(ax, ay), pack_h2(az, aw));
    *(uint2*)(o16 + (long long)w * 128 + lane * 4) = O;
}

// ---------------- fused CSR-fill + layer-0 aggregation (persistent, grid barrier) ----------------
__global__ void __launch_bounds__(FA_THREADS, 1)
k_fillagg(const void* __restrict__ edge, const float* __restrict__ xin,
          __half* __restrict__ o16, const float* __restrict__ eps_arr) {
    int tid = threadIdx.x;
    int gid = blockIdx.x * FA_THREADS + tid;
    int is64 = g_is64;
    for (int e = gid; e < N_EDGES; e += FA_BLOCKS * FA_THREADS) {
        int src = (int)load_idx(edge, e, is64);
        int dst = (int)load_idx(edge, (long long)N_EDGES + e, is64);
        int pos = atomicAdd(&g_cursor[dst], 1);
        g_srcs[pos] = src;
    }
    __syncthreads();
    if (tid == 0) {
        __threadfence();
        atomicAdd((int*)&g_gbar, 1);
        while (g_gbar < FA_BLOCKS) { }
    }
    __syncthreads();
    __threadfence();
    float eps = 1.0f + eps_arr[0];
    const float4* x4 = (const float4*)xin;
    int gw = gid >> 5, lane = tid & 31;
    const int NW = (FA_BLOCKS * FA_THREADS) / 32;
    for (int w = gw; w < N_NODES; w += NW)
        agg_node_f32<4>(x4, w, lane, eps, o16);
}

// ---------------- aggregation from fp16 input (layers 1-3), fp16 output ----------------
__global__ void k_agg(const __half* __restrict__ xin, __half* __restrict__ o16,
                      const float* __restrict__ eps_arr, int layer) {
    int w = (blockIdx.x * blockDim.x + threadIdx.x) >> 5;
    int lane = threadIdx.x & 31;
    if (w >= N_NODES) return;
    float eps = 1.0f + eps_arr[layer];
    const uint2* x2 = (const uint2*)xin;

    uint2 a = x2[(long long)w * 32 + lane];
    float2 a0 = __half22float2(*(__half2*)&a.x);
    float2 a1 = __half22float2(*(__half2*)&a.y);
    float ax = a0.x * eps, ay = a0.y * eps, az = a1.x * eps, aw = a1.y * eps;

    int e = g_rowoff[w], end = g_rowoff[w + 1];
    const int U = 8;
    for (; e + U - 1 < end; e += U) {
        int ss[U];
        uint2 vv[U];
        #pragma unroll
        for (int j = 0; j < U; j++) ss[j] = g_srcs[e + j];
        #pragma unroll
        for (int j = 0; j < U; j++) vv[j] = x2[(long long)ss[j] * 32 + lane];
        #pragma unroll
        for (int j = 0; j < U; j++) {
            float2 f0 = __half22float2(*(__half2*)&vv[j].x);
            float2 f1 = __half22float2(*(__half2*)&vv[j].y);
            ax += f0.x; ay += f0.y; az += f1.x; aw += f1.y;
        }
    }
    for (; e < end; e++) {
        uint2 v = x2[(long long)g_srcs[e] * 32 + lane];
        float2 f0 = __half22float2(*(__half2*)&v.x);
        float2 f1 = __half22float2(*(__half2*)&v.y);
        ax += f0.x; ay += f0.y; az += f1.x; aw += f1.y;
    }
    uint2 O = make_uint2(pack_h2(ax, ay), pack_h2(az, aw));
    *(uint2*)(o16 + (long long)w * 128 + lane * 4) = O;
}

// ---------------- fused per-layer GEMM pair (persistent HMMA, fp16 operands) ----------------
// Mainloop is SOFTWARE-PIPELINED: fragments for K-step ks+1 are loaded (ldsm4)
// BEFORE the MMAs of K-step ks issue, so ldsm latency hides behind MMA issue
// (all asm is volatile -> program order is the schedule).
// A single fp16 matrix (agg output / T1), W in fp16 hi/lo -> 2 combos per GEMM.
// Warp tile m64n32. A double-buffered via cp.async.

#define ASTR_B 272                      // padded row stride in bytes
#define MAT_B (128 * ASTR_B)            // 34816 B per 128-row matrix
#define SM_W1H 0
#define SM_W1L MAT_B
#define SM_W2H (2 * MAT_B)
#define SM_W2L (3 * MAT_B)
#define SM_AB(i) ((4 + (i)) * MAT_B)    // A fp16 double buffer
#define SM_TOTAL (6 * MAT_B)            // 208896 B -> 1 CTA/SM

__device__ __forceinline__ void ldsm4(unsigned* r, unsigned addr) {
    asm volatile("ldmatrix.sync.aligned.m8n8.x4.shared.b16 {%0,%1,%2,%3}, [%4];"
                 : "=r"(r[0]), "=r"(r[1]), "=r"(r[2]), "=r"(r[3]) : "r"(addr));
}
__device__ __forceinline__ void mma_f16(float* d, const unsigned* a, const unsigned* b) {
    asm volatile("mma.sync.aligned.m16n8k16.row.col.f32.f16.f16.f32 "
                 "{%0,%1,%2,%3}, {%4,%5,%6,%7}, {%8,%9}, {%0,%1,%2,%3};"
                 : "+f"(d[0]), "+f"(d[1]), "+f"(d[2]), "+f"(d[3])
                 : "r"(a[0]), "r"(a[1]), "r"(a[2]), "r"(a[3]), "r"(b[0]), "r"(b[1]));
}
__device__ __forceinline__ void cp16(unsigned saddr, const void* g, int nbytes) {
    asm volatile("cp.async.cg.shared.global [%0], [%1], 16, %2;"
                 :: "r"(saddr), "l"(g), "r"(nbytes) : "memory");
}

// issue cp.asyncs for one 128x128 fp16 A tile into buffer at sbuf
__device__ __forceinline__ void issue_A(const __half* __restrict__ A16,
                                        int row0, unsigned sbuf, int tid) {
    #pragma unroll
    for (int it = 0; it < 8; it++) {
        int i = tid + it * 256;                  // 0..2047 16B chunks (128 rows x 16)
        int r = i >> 4, c16 = i & 15;
        bool ok = (row0 + r) < N_NODES;
        const char* gp = (const char*)(A16 + (long long)(row0 + r) * 128) + c16 * 16;
        cp16(sbuf + (unsigned)(r * ASTR_B + c16 * 16), ok ? gp : (const char*)A16, ok ? 16 : 0);
    }
}

// load all fragments for one K-step
__device__ __forceinline__ void ld_frags(unsigned aBase, unsigned bH, unsigned bL,
                                         unsigned kb, unsigned av[4][4],
                                         unsigned bhr[2][4], unsigned blr[2][4]) {
    #pragma unroll
    for (int mt = 0; mt < 4; mt++)
        ldsm4(av[mt], aBase + (unsigned)(mt * 16 * ASTR_B) + kb);
    #pragma unroll
    for (int np = 0; np < 2; np++) {
        ldsm4(bhr[np], bH + (unsigned)(np * 16 * ASTR_B) + kb);
        ldsm4(blr[np], bL + (unsigned)(np * 16 * ASTR_B) + kb);
    }
}

// one 128x128 GEMM mainloop: m64n32 warp tile, 2 combos, pipelined fragments
__device__ __forceinline__ void gemm_tile(unsigned aBase, unsigned bH, unsigned bL,
                                          float acc[4][4][4]) {
    unsigned av[2][4][4], bhr[2][2][4], blr[2][2][4];
    ld_frags(aBase, bH, bL, 0u, av[0], bhr[0], blr[0]);
    #pragma unroll
    for (int ks = 0; ks < 8; ks++) {
        int cur = ks & 1, nxt = cur ^ 1;
        if (ks < 7)
            ld_frags(aBase, bH, bL, (unsigned)((ks + 1) * 32),
                     av[nxt], bhr[nxt], blr[nxt]);
        #pragma unroll
        for (int mt = 0; mt < 4; mt++)
            #pragma unroll
            for (int nt = 0; nt < 4; nt++)
                mma_f16(acc[mt][nt], av[cur][mt], &bhr[cur][nt >> 1][(nt & 1) * 2]);
        #pragma unroll
        for (int mt = 0; mt < 4; mt++)
            #pragma unroll
            for (int nt = 0; nt < 4; nt++)
                mma_f16(acc[mt][nt], av[cur][mt], &blr[cur][nt >> 1][(nt & 1) * 2]);
    }
}

__global__ void __launch_bounds__(256, 1)
k_layer(const __half* __restrict__ A16,
        const __half* __restrict__ W1h, const __half* __restrict__ W1l,
        const __half* __restrict__ W2h, const __half* __restrict__ W2l,
        const float* __restrict__ b1, const float* __restrict__ b2,
        __half* __restrict__ out16,
        const float* __restrict__ gamma, const float* __restrict__ beta,
        const float* __restrict__ mean,  const float* __restrict__ var) {
    extern __shared__ char smem[];
    unsigned sb;
    asm("{ .reg .u64 t; cvta.to.shared.u64 t, %1; cvt.u32.u64 %0, t; }" : "=r"(sb) : "l"(smem));
    int tid = threadIdx.x, wid = tid >> 5, lane = tid & 31;

    // stage 4 W matrices once + first A tile (group 0)
    #pragma unroll
    for (int it = 0; it < 32; it++) {
        int i = tid + it * 256;                  // 0..8191 16B chunks
        int m = i >> 11;                         // matrix 0..3
        int j = i & 2047;
        int r = j >> 4, c16 = j & 15;
        const __half* src = (m == 0) ? W1h : (m == 1) ? W1l : (m == 2) ? W2h : W2l;
        cp16(sb + (unsigned)(m * MAT_B + r * ASTR_B + c16 * 16),
             (const char*)(src + (long long)r * 128) + c16 * 16, 16);
    }
    int tile = blockIdx.x;
    if (tile < MTILES) issue_A(A16, tile * 128, sb + SM_AB(0), tid);
    asm volatile("cp.async.commit_group;" ::: "memory");

    int wr = wid & 1, wc = wid >> 1;      // warp tile: rows wr*64..+64, cols wc*32..+32
    int quad = lane >> 2, qi = lane & 3;

    // ldmatrix lane address components
    unsigned aoff = (unsigned)((wr * 64 + (lane & 15)) * ASTR_B + (lane >> 4) * 16);
    int bm = lane >> 3;
    int b_nt_off = bm >> 1;
    int b_kh = bm & 1;
    unsigned boff = (unsigned)((wc * 32 + b_nt_off * 8 + (lane & 7)) * ASTR_B + b_kh * 16);
    unsigned b1H = sb + SM_W1H + boff, b1L = sb + SM_W1L + boff;
    unsigned b2H = sb + SM_W2H + boff, b2L = sb + SM_W2L + boff;

    int bufi = 0;
    for (; tile < MTILES; tile += PERSIST_GRID, bufi ^= 1) {
        // prefetch next tile into the other buffer (overlaps both GEMMs)
        int next = tile + PERSIST_GRID;
        if (next < MTILES) issue_A(A16, next * 128, sb + SM_AB(bufi ^ 1), tid);
        asm volatile("cp.async.commit_group;" ::: "memory");
        asm volatile("cp.async.wait_group 1;" ::: "memory");   // current tile ready
        __syncthreads();

        unsigned aBase = sb + SM_AB(bufi) + aoff;

        // ---- GEMM1: acc = A @ W1t^T ----
        float acc[4][4][4];
        #pragma unroll
        for (int mt = 0; mt < 4; mt++)
            #pragma unroll
            for (int nt = 0; nt < 4; nt++)
                #pragma unroll
                for (int j = 0; j < 4; j++) acc[mt][nt][j] = 0.f;
        gemm_tile(aBase, b1H, b1L, acc);
        __syncthreads();   // all warps done reading A before overwrite

        // ---- T1 = relu(acc + b1) -> fp16 into current A buffer ----
        #pragma unroll
        for (int mt = 0; mt < 4; mt++) {
            int rr = wr * 64 + mt * 16 + quad;
            #pragma unroll
            for (int half = 0; half < 2; half++) {
                int r = rr + half * 8;
                #pragma unroll
                for (int nt = 0; nt < 4; nt++) {
                    int c = wc * 32 + nt * 8 + qi * 2;
                    float v0 = fmaxf(acc[mt][nt][half * 2] + __ldg(b1 + c), 0.f);
                    float v1 = fmaxf(acc[mt][nt][half * 2 + 1] + __ldg(b1 + c + 1), 0.f);
                    *(unsigned*)(smem + SM_AB(bufi) + r * ASTR_B + c * 2) = pack_h2(v0, v1);
                }
            }
        }
        __syncthreads();

        // ---- GEMM2: acc = T1 @ W2t^T ----
        #pragma unroll
        for (int mt = 0; mt < 4; mt++)
            #pragma unroll
            for (int nt = 0; nt < 4; nt++)
                #pragma unroll
                for (int j = 0; j < 4; j++) acc[mt][nt][j] = 0.f;
        gemm_tile(aBase, b2H, b2L, acc);
        __syncthreads();   // done reading T1; buffer free for next iter's prefetch

        // ---- epilogue: BN(relu(acc + b2)) -> fp16 out ----
        int row0 = tile * 128;
        #pragma unroll
        for (int mt = 0; mt < 4; mt++) {
            int r0 = row0 + wr * 64 + mt * 16 + quad;
            #pragma unroll
            for (int half = 0; half < 2; half++) {
                int r = r0 + half * 8;
                if (r >= N_NODES) continue;
                #pragma unroll
                for (int nt = 0; nt < 4; nt++) {
                    int c = wc * 32 + nt * 8 + qi * 2;
                    float v0 = fmaxf(acc[mt][nt][half * 2] + __ldg(b2 + c), 0.f);
                    float v1 = fmaxf(acc[mt][nt][half * 2 + 1] + __ldg(b2 + c + 1), 0.f);
                    float s0 = __ldg(gamma + c) * rsqrtf(__ldg(var + c) + 1e-5f);
                    float s1 = __ldg(gamma + c + 1) * rsqrtf(__ldg(var + c + 1) + 1e-5f);
                    v0 = (v0 - __ldg(mean + c)) * s0 + __ldg(beta + c);
                    v1 = (v1 - __ldg(mean + c + 1)) * s1 + __ldg(beta + c + 1);
                    *(unsigned*)(out16 + (long long)r * 128 + c) = pack_h2(v0, v1);
                }
            }
        }
    }
}

// ---------------- mean pool per graph (batch sorted, fp16 input) + scratch reset ----------------
__device__ __forceinline__ int lower_bound_batch(const void* batch, long long key, int is64) {
    int lo = 0, hi = N_NODES;
    while (lo < hi) {
        int mid = (lo + hi) >> 1;
        long long v = load_idx(batch, mid, is64);
        if (v < key) lo = mid + 1; else hi = mid;
    }
    return lo;
}

__global__ void k_pool(const __half* __restrict__ x, const void* __restrict__ batch) {
    int g = blockIdx.x;
    int f = threadIdx.x;
    __shared__ int s_beg, s_end;
    if (f == 0) {
        int is64 = g_is64;
        s_beg = lower_bound_batch(batch, g, is64);
        s_end = lower_bound_batch(batch, g + 1, is64);
    }
    __syncthreads();
    int beg = s_beg, end = s_end;
    float s = 0.f;
    for (int r = beg; r < end; r++) s += __half2float(x[(long long)r * HID + f]);
    float cnt = (float)(end - beg);
    g_pooled[g * HID + f] = s / fmaxf(cnt, 1.0f);

    // tail: reset CSR scratch + barriers for the next graph replay
    int gt = g * HID + f;
    for (int i = gt; i < N_NODES + 1; i += N_GRAPHS * HID) g_rowoff[i] = 0;
    if (gt < SCAN_B) g_bflag[gt] = 0;
    if (gt == 0) g_gbar = 0;
}

// ---------------- head: relu(pooled@W1+b1) @ W2 + b2, log_softmax ----------------
__global__ void k_head(const float* __restrict__ W1, const float* __restrict__ b1,
                       const float* __restrict__ W2, const float* __restrict__ b2,
                       float* __restrict__ out) {
    int g = blockIdx.x;
    int t = threadIdx.x;
    __shared__ float sp[HID], sh[HID], sl[OUT_DIM];
    __shared__ float smax, slse;
    sp[t] = g_pooled[g * HID + t];
    __syncthreads();
    float acc = b1[t];
    #pragma unroll 8
    for (int k = 0; k < HID; k++) acc += sp[k] * W1[k * HID + t];
    sh[t] = fmaxf(acc, 0.f);
    __syncthreads();
    if (t < OUT_DIM) {
        float a = b2[t];
        #pragma unroll 8
        for (int k = 0; k < HID; k++) a += sh[k] * W2[k * OUT_DIM + t];
        sl[t] = a;
    }
    __syncthreads();
    if (t == 0) {
        float m = -1e30f;
        for (int o = 0; o < OUT_DIM; o++) m = fmaxf(m, sl[o]);
        float s = 0.f;
        for (int o = 0; o < OUT_DIM; o++) s += expf(sl[o] - m);
        smax = m; slse = logf(s);
    }
    __syncthreads();
    if (t < OUT_DIM) out[g * OUT_DIM + t] = sl[t] - smax - slse;
}

// ---------------- launch ----------------
extern "C" void kernel_launch(void* const* d_in, const int* in_sizes, int n_in,
                              void* d_out, int out_size) {
    const float* x      = (const float*)d_in[0];
    const void*  edge   = d_in[1];
    const void*  batch  = d_in[2];
    const float* W1s    = (const float*)d_in[3];
    const float* b1s    = (const float*)d_in[4];
    const float* W2s    = (const float*)d_in[5];
    const float* b2s    = (const float*)d_in[6];
    const float* gammas = (const float*)d_in[7];
    const float* betas  = (const float*)d_in[8];
    const float* means  = (const float*)d_in[9];
    const float* vars   = (const float*)d_in[10];
    const float* epsarr = (const float*)d_in[11];
    const float* lin1W  = (const float*)d_in[12];
    const float* lin1b  = (const float*)d_in[13];
    const float* lin2W  = (const float*)d_in[14];
    const float* lin2b  = (const float*)d_in[15];
    float* out = (float*)d_out;

    __half *X16, *B16, *Wh16, *Wl16;
    cudaGetSymbolAddress((void**)&X16, g_X16);
    cudaGetSymbolAddress((void**)&B16, g_B16);
    cudaGetSymbolAddress((void**)&Wh16, g_Wh16);
    cudaGetSymbolAddress((void**)&Wl16, g_Wl16);

    cudaFuncSetAttribute(k_layer, cudaFuncAttributeMaxDynamicSharedMemorySize, SM_TOTAL);

    // CSR build + weight prep; fillagg fuses fill with layer-0 agg so that
    // k_layer is launch #4 (the ncu capture slot)
    k_count<<<EDGE_BLOCKS + WPREP_BLOCKS, 256>>>(edge, W1s, W2s);
    k_scanall<<<SCAN_B, 1024>>>();
    k_fillagg<<<FA_BLOCKS, FA_THREADS>>>(edge, x, B16, epsarr);

    const int agg_blocks = (N_NODES * 32 + 255) / 256;

    for (int l = 0; l < N_LAYERS; l++) {
        if (l > 0)
            k_agg<<<agg_blocks, 256>>>(X16, B16, epsarr, l);
        k_layer<<<PERSIST_GRID, 256, SM_TOTAL>>>(
            B16,
            Wh16 + (l * 2) * 16384, Wl16 + (l * 2) * 16384,
            Wh16 + (l * 2 + 1) * 16384, Wl16 + (l * 2 + 1) * 16384,
            b1s + l * HID, b2s + l * HID,
            X16,
            gammas + l * HID, betas + l * HID, means + l * HID, vars + l * HID);
    }

    k_pool<<<N_GRAPHS, HID>>>(X16, batch);
    k_head<<<N_GRAPHS, HID>>>(lin1W, lin1b, lin2W, lin2b, out);
}